// round 1
// baseline (speedup 1.0000x reference)
#include <cuda_runtime.h>
#include <math.h>

#define NB 16
#define NP 1024          // S*S
#define CF 768
#define CC 512
#define HW 28
#define KT 32

// ---------------- scratch (device globals; no allocation) ----------------
__device__ float g_F1 [NB*NP*CF];   // norm(sample(orig_feats,     c1))
__device__ float g_C1 [NB*NP*CC];   // norm(sample(orig_code,      c1))
__device__ float g_F2p[NB*NP*CF];   // norm(sample(orig_feats_pos, c2))
__device__ float g_C2p[NB*NP*CC];
__device__ float g_Fn0[NB*NP*CF];   // norm(sample(orig_feats[perm0], c2))
__device__ float g_Cn0[NB*NP*CC];
__device__ float g_Fn1[NB*NP*CF];
__device__ float g_Cn1[NB*NP*CC];

__device__ float  g_rowfd[4*NB*NP];   // per helper: sum_q fd[b,p,q]
__device__ float  g_rowrc[4*NB*NP];   // per helper: sum_q relu(cd)[b,p,q]
__device__ double g_scal[4];          // per helper: sum relu(cd)*fd

__device__ __forceinline__ float* dst_ptr(int id) {
    switch (id) {
        case 0: return g_F1;  case 1: return g_C1;
        case 2: return g_F2p; case 3: return g_C2p;
        case 4: return g_Fn0; case 5: return g_Cn0;
        case 6: return g_Fn1; default: return g_Cn1;
    }
}

// ---------------- zero the accumulators ----------------
__global__ void zero_kernel() {
    int i = blockIdx.x * 256 + threadIdx.x;
    if (i < 4*NB*NP) { g_rowfd[i] = 0.f; g_rowrc[i] = 0.f; }
    if (i < 4) g_scal[i] = 0.0;
}

// ---------------- bilinear sample + channel-normalize ----------------
// One block per (b,p). Output layout: dst[(b*NP+p)*C + c].
__global__ void __launch_bounds__(256) sample_norm_kernel(
    const float* __restrict__ src,     // (B, C, 28, 28), batch indexed via perm or identity
    const float* __restrict__ coords,  // (B, 1024, 2) in [0,1]
    const int*   __restrict__ perm,    // length B, or nullptr
    int dst_id, int C)
{
    float* dst = dst_ptr(dst_id);
    int bp = blockIdx.x;
    int b = bp >> 10, p = bp & 1023;
    int bs = perm ? perm[b] : b;

    float cx = coords[(size_t)(b*NP + p)*2 + 0] * 2.f - 1.f;
    float cy = coords[(size_t)(b*NP + p)*2 + 1] * 2.f - 1.f;
    float x = (cx + 1.f) * 0.5f * (float)(HW - 1);
    float y = (cy + 1.f) * 0.5f * (float)(HW - 1);
    float x0 = floorf(x), y0 = floorf(y);
    float wx = x - x0,    wy = y - y0;
    int x0c = (int)fminf(fmaxf(x0,       0.f), (float)(HW-1));
    int x1c = (int)fminf(fmaxf(x0 + 1.f, 0.f), (float)(HW-1));
    int y0c = (int)fminf(fmaxf(y0,       0.f), (float)(HW-1));
    int y1c = (int)fminf(fmaxf(y0 + 1.f, 0.f), (float)(HW-1));
    // Ia:(y0,x0) Ib:(y1,x0) Ic:(y0,x1) Id:(y1,x1)
    float w00 = (1.f-wx)*(1.f-wy);
    float w01 = (1.f-wx)*wy;
    float w10 = wx*(1.f-wy);
    float w11 = wx*wy;

    const float* sb = src + (size_t)bs * C * (HW*HW);
    int o00 = y0c*HW + x0c, o01 = y1c*HW + x0c;
    int o10 = y0c*HW + x1c, o11 = y1c*HW + x1c;

    int tid = threadIdx.x;
    int nv = C >> 8;               // 3 for CF, 2 for CC
    float vals[3];
    float ssq = 0.f;
    #pragma unroll
    for (int i = 0; i < 3; i++) {
        if (i < nv) {
            int c = i*256 + tid;
            const float* ch = sb + (size_t)c * (HW*HW);
            float v = w00*ch[o00] + w01*ch[o01] + w10*ch[o10] + w11*ch[o11];
            vals[i] = v;
            ssq += v * v;
        }
    }
    // block reduce sum of squares
    #pragma unroll
    for (int off = 16; off; off >>= 1) ssq += __shfl_xor_sync(0xffffffffu, ssq, off);
    __shared__ float sred[8];
    if ((tid & 31) == 0) sred[tid >> 5] = ssq;
    __syncthreads();
    if (tid < 8) {
        float v = sred[tid];
        #pragma unroll
        for (int off = 4; off; off >>= 1) v += __shfl_xor_sync(0xffu, v, off);
        if (tid == 0) sred[0] = v;
    }
    __syncthreads();
    float scale = 1.f / fmaxf(sqrtf(sred[0]), 1e-10f);

    float* db = dst + (size_t)(b*NP + p) * C;
    #pragma unroll
    for (int i = 0; i < 3; i++)
        if (i < nv) db[i*256 + tid] = vals[i] * scale;
}

// ---------------- fused correlation GEMM + reductions ----------------
// 64x64 output tile, 256 threads, 4x4 per thread, K-tile 32.
__device__ __forceinline__ void mm_phase(
    const float* __restrict__ Ab, const float* __restrict__ Bb, int C,
    float (&acc)[4][4], float (*As)[68], float (*Bs)[68],
    int tid, int tx, int ty)
{
    for (int c0 = 0; c0 < C; c0 += KT) {
        #pragma unroll
        for (int it = 0; it < 8; it++) {
            int idx = it*256 + tid;
            int r = idx >> 5, k = idx & 31;
            As[k][r] = Ab[(size_t)r*C + c0 + k];
            Bs[k][r] = Bb[(size_t)r*C + c0 + k];
        }
        __syncthreads();
        #pragma unroll
        for (int k = 0; k < KT; k++) {
            float a[4], bv[4];
            #pragma unroll
            for (int i = 0; i < 4; i++) a[i]  = As[k][ty*4 + i];
            #pragma unroll
            for (int j = 0; j < 4; j++) bv[j] = Bs[k][tx*4 + j];
            #pragma unroll
            for (int i = 0; i < 4; i++)
                #pragma unroll
                for (int j = 0; j < 4; j++)
                    acc[i][j] += a[i] * bv[j];
        }
        __syncthreads();
    }
}

__global__ void __launch_bounds__(256) corr_kernel(int slot)
{
    const float* F2; const float* C2;
    switch (slot) {
        case 0:  F2 = g_F1;  C2 = g_C1;  break;
        case 1:  F2 = g_F2p; C2 = g_C2p; break;
        case 2:  F2 = g_Fn0; C2 = g_Cn0; break;
        default: F2 = g_Fn1; C2 = g_Cn1; break;
    }
    const float* F1 = g_F1;
    const float* C1 = g_C1;

    int b  = blockIdx.z;
    int p0 = blockIdx.y * 64;
    int q0 = blockIdx.x * 64;
    int tid = threadIdx.x;
    int tx = tid & 15, ty = tid >> 4;

    __shared__ float As[KT][68];
    __shared__ float Bs[KT][68];

    float fd[4][4]  = {};
    float cdv[4][4] = {};
    mm_phase(F1 + ((size_t)b*NP + p0)*CF, F2 + ((size_t)b*NP + q0)*CF, CF, fd,  As, Bs, tid, tx, ty);
    mm_phase(C1 + ((size_t)b*NP + p0)*CC, C2 + ((size_t)b*NP + q0)*CC, CC, cdv, As, Bs, tid, tx, ty);

    // per-thread partials
    float rowf[4], rowr[4];
    double lsum = 0.0;
    #pragma unroll
    for (int i = 0; i < 4; i++) {
        rowf[i] = 0.f; rowr[i] = 0.f;
        #pragma unroll
        for (int j = 0; j < 4; j++) {
            float rc = fmaxf(cdv[i][j], 0.f);
            rowf[i] += fd[i][j];
            rowr[i] += rc;
            lsum += (double)(rc * fd[i][j]);
        }
    }
    // reduce row partials across the 16 tx lanes sharing each ty (within warp halves)
    #pragma unroll
    for (int off = 1; off < 16; off <<= 1) {
        #pragma unroll
        for (int i = 0; i < 4; i++) {
            rowf[i] += __shfl_xor_sync(0xffffffffu, rowf[i], off);
            rowr[i] += __shfl_xor_sync(0xffffffffu, rowr[i], off);
        }
    }
    if (tx == 0) {
        int base = slot*NB*NP + b*NP + p0 + ty*4;
        #pragma unroll
        for (int i = 0; i < 4; i++) {
            atomicAdd(&g_rowfd[base + i], rowf[i]);
            atomicAdd(&g_rowrc[base + i], rowr[i]);
        }
    }
    // block-reduce lsum -> one double atomic per block
    #pragma unroll
    for (int off = 16; off; off >>= 1) lsum += __shfl_xor_sync(0xffffffffu, lsum, off);
    __shared__ double dred[8];
    if ((tid & 31) == 0) dred[tid >> 5] = lsum;
    __syncthreads();
    if (tid < 8) {
        double v = dred[tid];
        #pragma unroll
        for (int off = 4; off; off >>= 1) v += __shfl_xor_sync(0xffu, v, off);
        if (tid == 0) atomicAdd(&g_scal[slot], v);
    }
}

// ---------------- finalize: combine scalars -> 3 outputs ----------------
__global__ void finalize_kernel(float* out)
{
    __shared__ double sred[3][8];
    __shared__ double res[4][3];
    int tid = threadIdx.x;
    for (int s = 0; s < 4; s++) {
        double tf = 0.0, tr = 0.0, cx = 0.0;
        const float* rf = g_rowfd + s*NB*NP;
        const float* rr = g_rowrc + s*NB*NP;
        for (int i = tid; i < NB*NP; i += 256) {
            double f = (double)rf[i], r = (double)rr[i];
            tf += f; tr += r; cx += f * r;
        }
        #pragma unroll
        for (int off = 16; off; off >>= 1) {
            tf += __shfl_xor_sync(0xffffffffu, tf, off);
            tr += __shfl_xor_sync(0xffffffffu, tr, off);
            cx += __shfl_xor_sync(0xffffffffu, cx, off);
        }
        if ((tid & 31) == 0) {
            sred[0][tid >> 5] = tf; sred[1][tid >> 5] = tr; sred[2][tid >> 5] = cx;
        }
        __syncthreads();
        if (tid < 8) {
            double a = sred[0][tid], bv = sred[1][tid], c = sred[2][tid];
            #pragma unroll
            for (int off = 4; off; off >>= 1) {
                a  += __shfl_xor_sync(0xffu, a,  off);
                bv += __shfl_xor_sync(0xffu, bv, off);
                c  += __shfl_xor_sync(0xffu, c,  off);
            }
            if (tid == 0) { res[s][0] = a; res[s][1] = bv; res[s][2] = c; }
        }
        __syncthreads();
    }
    if (tid == 0) {
        const double BPQ = (double)NB * (double)NP * (double)NP;
        const double Q   = (double)NP;
        const double shifts[4] = {0.18, 0.12, 0.46, 0.46};
        double loss[4];
        for (int s = 0; s < 4; s++) {
            double tf = res[s][0], tr = res[s][1], cx = res[s][2];
            double A  = g_scal[s];
            double gm = tf / BPQ;
            // mean( -relu(cd) * (fd - rowmean(fd) + gm - shift) )
            loss[s] = (-A + cx / Q) / BPQ - (gm - shifts[s]) * (tr / BPQ);
        }
        out[0] = (float)loss[0];
        out[1] = (float)loss[1];
        out[2] = (float)(0.5 * (loss[2] + loss[3]));
    }
}

// ---------------- launch ----------------
extern "C" void kernel_launch(void* const* d_in, const int* in_sizes, int n_in,
                              void* d_out, int out_size)
{
    const float* orig_feats     = (const float*)d_in[0];
    const float* orig_feats_pos = (const float*)d_in[1];
    // d_in[2], d_in[3]: salience (unused)
    const float* orig_code      = (const float*)d_in[4];
    const float* orig_code_pos  = (const float*)d_in[5];
    // d_in[6], d_in[7]: depth (unused)
    const float* coords1        = (const float*)d_in[8];
    const float* coords2        = (const float*)d_in[9];
    const int*   perms          = (const int*)d_in[10];
    float* out = (float*)d_out;

    zero_kernel<<<256, 256>>>();

    sample_norm_kernel<<<NB*NP, 256>>>(orig_feats,     coords1, nullptr,   0, CF);
    sample_norm_kernel<<<NB*NP, 256>>>(orig_code,      coords1, nullptr,   1, CC);
    sample_norm_kernel<<<NB*NP, 256>>>(orig_feats_pos, coords2, nullptr,   2, CF);
    sample_norm_kernel<<<NB*NP, 256>>>(orig_code_pos,  coords2, nullptr,   3, CC);
    sample_norm_kernel<<<NB*NP, 256>>>(orig_feats,     coords2, perms,     4, CF);
    sample_norm_kernel<<<NB*NP, 256>>>(orig_code,      coords2, perms,     5, CC);
    sample_norm_kernel<<<NB*NP, 256>>>(orig_feats,     coords2, perms+NB,  6, CF);
    sample_norm_kernel<<<NB*NP, 256>>>(orig_code,      coords2, perms+NB,  7, CC);

    dim3 grid(NP/64, NP/64, NB);   // (16,16,16)
    corr_kernel<<<grid, 256>>>(0);
    corr_kernel<<<grid, 256>>>(1);
    corr_kernel<<<grid, 256>>>(2);
    corr_kernel<<<grid, 256>>>(3);

    finalize_kernel<<<1, 256>>>(out);
}

// round 3
// speedup vs baseline: 4.9620x; 4.9620x over previous
#include <cuda_runtime.h>
#include <cuda_bf16.h>
#include <cstdint>
#include <math.h>

#define NB 16
#define NP 1024
#define CF 768
#define CC 512
#define HW 28
#define PIX 784
#define KT 32
#define STR 40            // padded smem k-stride (elements): conflict-free frag loads

// ======================= scratch (device globals) =======================
__device__ float g_Ft [NB * PIX * CF];
__device__ float g_Fpt[NB * PIX * CF];
__device__ float g_Ct [NB * PIX * CC];
__device__ float g_Cpt[NB * PIX * CC];

__device__ __nv_bfloat16 g_F1 [NB * NP * CF];
__device__ __nv_bfloat16 g_C1 [NB * NP * CC];
__device__ __nv_bfloat16 g_F2p[NB * NP * CF];
__device__ __nv_bfloat16 g_C2p[NB * NP * CC];
__device__ __nv_bfloat16 g_Fn0[NB * NP * CF];
__device__ __nv_bfloat16 g_Cn0[NB * NP * CC];
__device__ __nv_bfloat16 g_Fn1[NB * NP * CF];
__device__ __nv_bfloat16 g_Cn1[NB * NP * CC];

__device__ float  g_rowfd[4 * NB * NP];
__device__ float  g_rowrc[4 * NB * NP];
__device__ double g_scal[4];

__device__ __forceinline__ __nv_bfloat16* dst_ptr(int id) {
    switch (id) {
        case 0: return g_F1;  case 1: return g_C1;
        case 2: return g_F2p; case 3: return g_C2p;
        case 4: return g_Fn0; case 5: return g_Cn0;
        case 6: return g_Fn1; default: return g_Cn1;
    }
}
__device__ __forceinline__ float* tsrc_ptr(int id) {
    switch (id) {
        case 0: return g_Ft;  case 1: return g_Ct;
        case 2: return g_Fpt; default: return g_Cpt;
    }
}

// ======================= zero =======================
__global__ void zero_kernel() {
    int i = blockIdx.x * 256 + threadIdx.x;
    if (i < 4 * NB * NP) { g_rowfd[i] = 0.f; g_rowrc[i] = 0.f; }
    if (i < 4) g_scal[i] = 0.0;
}

// ======================= transpose (B,C,784) -> (B,784,C) =======================
__global__ void __launch_bounds__(256) transpose_kernel(const float* __restrict__ in,
                                                        int dst_id, int C) {
    float* out = tsrc_ptr(dst_id);
    __shared__ float t[32][33];
    int b  = blockIdx.z;
    int c0 = blockIdx.y * 32;
    int h0 = blockIdx.x * 32;
    int x = threadIdx.x, y = threadIdx.y;   // 32x8
    #pragma unroll
    for (int i = 0; i < 32; i += 8) {
        int c = c0 + y + i, h = h0 + x;
        if (h < PIX) t[y + i][x] = in[((size_t)b * C + c) * PIX + h];
    }
    __syncthreads();
    #pragma unroll
    for (int i = 0; i < 32; i += 8) {
        int h = h0 + y + i, c = c0 + x;
        if (h < PIX) out[((size_t)b * PIX + h) * C + c] = t[x][y + i];
    }
}

// ======================= bilinear sample + normalize -> bf16 =======================
__global__ void __launch_bounds__(256) sample_norm_kernel(
    int src_id,                        // transposed source (B,784,C)
    const float* __restrict__ coords,  // (B, 1024, 2) in [0,1]
    const int*   __restrict__ perm,
    int dst_id, int C)
{
    const float* T = tsrc_ptr(src_id);
    __nv_bfloat16* dst = dst_ptr(dst_id);
    int bp = blockIdx.x;
    int b = bp >> 10, p = bp & 1023;
    int bs = perm ? perm[b] : b;

    float u = coords[(size_t)(b * NP + p) * 2 + 0];
    float v = coords[(size_t)(b * NP + p) * 2 + 1];
    float x = ((u * 2.f - 1.f) + 1.f) * 0.5f * (float)(HW - 1);
    float y = ((v * 2.f - 1.f) + 1.f) * 0.5f * (float)(HW - 1);
    float x0 = floorf(x), y0 = floorf(y);
    float wx = x - x0, wy = y - y0;
    int x0c = (int)fminf(fmaxf(x0,       0.f), (float)(HW - 1));
    int x1c = (int)fminf(fmaxf(x0 + 1.f, 0.f), (float)(HW - 1));
    int y0c = (int)fminf(fmaxf(y0,       0.f), (float)(HW - 1));
    int y1c = (int)fminf(fmaxf(y0 + 1.f, 0.f), (float)(HW - 1));
    float w00 = (1.f - wx) * (1.f - wy);
    float w01 = (1.f - wx) * wy;
    float w10 = wx * (1.f - wy);
    float w11 = wx * wy;

    const float4* r00 = (const float4*)(T + ((size_t)bs * PIX + y0c * HW + x0c) * C);
    const float4* r01 = (const float4*)(T + ((size_t)bs * PIX + y1c * HW + x0c) * C);
    const float4* r10 = (const float4*)(T + ((size_t)bs * PIX + y0c * HW + x1c) * C);
    const float4* r11 = (const float4*)(T + ((size_t)bs * PIX + y1c * HW + x1c) * C);

    int tid = threadIdx.x;
    int n4 = C >> 2;
    float4 val = make_float4(0.f, 0.f, 0.f, 0.f);
    float ssq = 0.f;
    if (tid < n4) {
        float4 a = r00[tid], bq = r01[tid], c2 = r10[tid], d = r11[tid];
        val.x = w00 * a.x + w01 * bq.x + w10 * c2.x + w11 * d.x;
        val.y = w00 * a.y + w01 * bq.y + w10 * c2.y + w11 * d.y;
        val.z = w00 * a.z + w01 * bq.z + w10 * c2.z + w11 * d.z;
        val.w = w00 * a.w + w01 * bq.w + w10 * c2.w + w11 * d.w;
        ssq = val.x * val.x + val.y * val.y + val.z * val.z + val.w * val.w;
    }
    #pragma unroll
    for (int off = 16; off; off >>= 1) ssq += __shfl_xor_sync(0xffffffffu, ssq, off);
    __shared__ float sred[8];
    if ((tid & 31) == 0) sred[tid >> 5] = ssq;
    __syncthreads();
    if (tid < 8) {
        float s = sred[tid];
        #pragma unroll
        for (int off = 4; off; off >>= 1) s += __shfl_xor_sync(0xffu, s, off);
        if (tid == 0) sred[0] = s;
    }
    __syncthreads();
    float scale = 1.f / fmaxf(sqrtf(sred[0]), 1e-10f);

    if (tid < n4) {
        __nv_bfloat162 lo = __floats2bfloat162_rn(val.x * scale, val.y * scale);
        __nv_bfloat162 hi = __floats2bfloat162_rn(val.z * scale, val.w * scale);
        uint2 o;
        o.x = *(uint32_t*)&lo;
        o.y = *(uint32_t*)&hi;
        *(uint2*)(dst + ((size_t)(b * NP + p)) * C + tid * 4) = o;
    }
}

// ======================= HMMA correlation kernel =======================
// mma.sync m16n8k16 bf16 (arch-portable; no tcgen05 on this build target).
// CTA: 128x128 tile, 512 threads = 16 warps (4x4), warp tile 32x32.
// fd accums over CF (24 K-chunks), cd accums over CC (16 K-chunks).

__device__ __forceinline__ void mma_bf16(float (&d)[4], const uint32_t (&a)[4],
                                         uint32_t b0, uint32_t b1) {
    asm volatile(
        "mma.sync.aligned.m16n8k16.row.col.f32.bf16.bf16.f32 "
        "{%0,%1,%2,%3}, {%4,%5,%6,%7}, {%8,%9}, {%0,%1,%2,%3};\n"
        : "+f"(d[0]), "+f"(d[1]), "+f"(d[2]), "+f"(d[3])
        : "r"(a[0]), "r"(a[1]), "r"(a[2]), "r"(a[3]), "r"(b0), "r"(b1));
}

__device__ __forceinline__ void warp_mma_tile(
    const __nv_bfloat16* __restrict__ As, const __nv_bfloat16* __restrict__ Bs,
    int wm, int wn, int g, int t, float (&acc)[2][4][4])
{
    #pragma unroll
    for (int ks = 0; ks < 2; ks++) {
        int k0 = ks * 16 + 2 * t;
        uint32_t a[2][4];
        #pragma unroll
        for (int i = 0; i < 2; i++) {
            const __nv_bfloat16* base = As + (wm * 32 + i * 16 + g) * STR + k0;
            a[i][0] = *(const uint32_t*)(base);
            a[i][1] = *(const uint32_t*)(base + 8 * STR);
            a[i][2] = *(const uint32_t*)(base + 8);
            a[i][3] = *(const uint32_t*)(base + 8 * STR + 8);
        }
        #pragma unroll
        for (int j = 0; j < 4; j++) {
            const __nv_bfloat16* nb = Bs + (wn * 32 + j * 8 + g) * STR + k0;
            uint32_t b0 = *(const uint32_t*)(nb);
            uint32_t b1 = *(const uint32_t*)(nb + 8);
            #pragma unroll
            for (int i = 0; i < 2; i++)
                mma_bf16(acc[i][j], a[i], b0, b1);
        }
    }
}

__global__ void __launch_bounds__(512, 1) corr_mma_kernel()
{
    int slot = blockIdx.z >> 4;
    int b    = blockIdx.z & 15;
    int p0   = blockIdx.y * 128;
    int q0   = blockIdx.x * 128;

    const __nv_bfloat16 *Bf, *Bc;
    switch (slot) {
        case 0:  Bf = g_F1;  Bc = g_C1;  break;
        case 1:  Bf = g_F2p; Bc = g_C2p; break;
        case 2:  Bf = g_Fn0; Bc = g_Cn0; break;
        default: Bf = g_Fn1; Bc = g_Cn1; break;
    }
    const __nv_bfloat16* Af_r = g_F1 + (size_t)(b * NP + p0) * CF;
    const __nv_bfloat16* Ac_r = g_C1 + (size_t)(b * NP + p0) * CC;
    const __nv_bfloat16* Bf_r = Bf   + (size_t)(b * NP + q0) * CF;
    const __nv_bfloat16* Bc_r = Bc   + (size_t)(b * NP + q0) * CC;

    __shared__ __align__(16) __nv_bfloat16 smA[2][128 * STR];
    __shared__ __align__(16) __nv_bfloat16 smB[2][128 * STR];
    __shared__ float  red_f[128];
    __shared__ float  red_r[128];
    __shared__ double red_d[16];

    int tid = threadIdx.x;
    int wid = tid >> 5, lane = tid & 31;
    int g = lane >> 2, t = lane & 3;
    int wm = wid >> 2, wn = wid & 3;
    int lrow = tid >> 2, lseg = tid & 3;    // loader: 128 rows x 4 segs of 8 bf16

    if (tid < 128) { red_f[tid] = 0.f; red_r[tid] = 0.f; }

    float facc[2][4][4] = {};
    float cacc[2][4][4] = {};

    #define NCH 40  // 24 feats + 16 code
    auto load_src = [&](int c, uint4& ra, uint4& rb) {
        if (c < 24) {
            size_t off = (size_t)lrow * CF + c * KT + lseg * 8;
            ra = *(const uint4*)(Af_r + off);
            rb = *(const uint4*)(Bf_r + off);
        } else {
            size_t off = (size_t)lrow * CC + (c - 24) * KT + lseg * 8;
            ra = *(const uint4*)(Ac_r + off);
            rb = *(const uint4*)(Bc_r + off);
        }
    };

    uint4 ra, rb;
    load_src(0, ra, rb);
    *(uint4*)&smA[0][lrow * STR + lseg * 8] = ra;
    *(uint4*)&smB[0][lrow * STR + lseg * 8] = rb;
    __syncthreads();

    for (int c = 0; c < NCH; c++) {
        int buf = c & 1;
        if (c + 1 < NCH) load_src(c + 1, ra, rb);
        if (c < 24) warp_mma_tile(smA[buf], smB[buf], wm, wn, g, t, facc);
        else        warp_mma_tile(smA[buf], smB[buf], wm, wn, g, t, cacc);
        if (c + 1 < NCH) {
            int nb = (c + 1) & 1;
            *(uint4*)&smA[nb][lrow * STR + lseg * 8] = ra;
            *(uint4*)&smB[nb][lrow * STR + lseg * 8] = rb;
        }
        __syncthreads();
    }

    // -------- epilogue: row sums + scalar, all in-register --------
    float lsum = 0.f;
    float rf[2][2] = {}, rr[2][2] = {};
    #pragma unroll
    for (int i = 0; i < 2; i++) {
        #pragma unroll
        for (int j = 0; j < 4; j++) {
            float f0 = facc[i][j][0], f1 = facc[i][j][1];
            float f2 = facc[i][j][2], f3 = facc[i][j][3];
            float r0 = fmaxf(cacc[i][j][0], 0.f), r1 = fmaxf(cacc[i][j][1], 0.f);
            float r2 = fmaxf(cacc[i][j][2], 0.f), r3 = fmaxf(cacc[i][j][3], 0.f);
            rf[i][0] += f0 + f1;  rf[i][1] += f2 + f3;
            rr[i][0] += r0 + r1;  rr[i][1] += r2 + r3;
            lsum += r0 * f0 + r1 * f1 + r2 * f2 + r3 * f3;
        }
    }
    // reduce over the 4 lanes (t) sharing each row g
    #pragma unroll
    for (int off = 1; off < 4; off <<= 1) {
        #pragma unroll
        for (int i = 0; i < 2; i++) {
            rf[i][0] += __shfl_xor_sync(0xffffffffu, rf[i][0], off);
            rf[i][1] += __shfl_xor_sync(0xffffffffu, rf[i][1], off);
            rr[i][0] += __shfl_xor_sync(0xffffffffu, rr[i][0], off);
            rr[i][1] += __shfl_xor_sync(0xffffffffu, rr[i][1], off);
        }
    }
    if (t == 0) {
        #pragma unroll
        for (int i = 0; i < 2; i++) {
            int r0 = wm * 32 + i * 16 + g;
            atomicAdd(&red_f[r0],     rf[i][0]);
            atomicAdd(&red_f[r0 + 8], rf[i][1]);
            atomicAdd(&red_r[r0],     rr[i][0]);
            atomicAdd(&red_r[r0 + 8], rr[i][1]);
        }
    }
    // scalar: warp reduce then block reduce in double
    #pragma unroll
    for (int off = 16; off; off >>= 1) lsum += __shfl_xor_sync(0xffffffffu, lsum, off);
    if (lane == 0) red_d[wid] = (double)lsum;
    __syncthreads();

    if (tid == 0) {
        double s = 0.0;
        #pragma unroll
        for (int w = 0; w < 16; w++) s += red_d[w];
        atomicAdd(&g_scal[slot], s);
    }
    if (tid < 128) {
        int gi = slot * NB * NP + b * NP + p0 + tid;
        atomicAdd(&g_rowfd[gi], red_f[tid]);
        atomicAdd(&g_rowrc[gi], red_r[tid]);
    }
}

// ======================= finalize =======================
__global__ void finalize_kernel(float* out)
{
    __shared__ double sred[3][8];
    __shared__ double res[4][3];
    int tid = threadIdx.x;
    for (int s = 0; s < 4; s++) {
        double tf = 0.0, tr = 0.0, cx = 0.0;
        const float* rf = g_rowfd + s * NB * NP;
        const float* rr = g_rowrc + s * NB * NP;
        for (int i = tid; i < NB * NP; i += 256) {
            double f = (double)rf[i], r = (double)rr[i];
            tf += f; tr += r; cx += f * r;
        }
        #pragma unroll
        for (int off = 16; off; off >>= 1) {
            tf += __shfl_xor_sync(0xffffffffu, tf, off);
            tr += __shfl_xor_sync(0xffffffffu, tr, off);
            cx += __shfl_xor_sync(0xffffffffu, cx, off);
        }
        if ((tid & 31) == 0) { sred[0][tid >> 5] = tf; sred[1][tid >> 5] = tr; sred[2][tid >> 5] = cx; }
        __syncthreads();
        if (tid < 8) {
            double a = sred[0][tid], bv = sred[1][tid], c = sred[2][tid];
            #pragma unroll
            for (int off = 4; off; off >>= 1) {
                a  += __shfl_xor_sync(0xffu, a,  off);
                bv += __shfl_xor_sync(0xffu, bv, off);
                c  += __shfl_xor_sync(0xffu, c,  off);
            }
            if (tid == 0) { res[s][0] = a; res[s][1] = bv; res[s][2] = c; }
        }
        __syncthreads();
    }
    if (tid == 0) {
        const double BPQ = (double)NB * (double)NP * (double)NP;
        const double Q   = (double)NP;
        const double shifts[4] = {0.18, 0.12, 0.46, 0.46};
        double loss[4];
        for (int s = 0; s < 4; s++) {
            double tf = res[s][0], tr = res[s][1], cx = res[s][2];
            double A  = g_scal[s];
            double gm = tf / BPQ;
            loss[s] = (-A + cx / Q) / BPQ - (gm - shifts[s]) * (tr / BPQ);
        }
        out[0] = (float)loss[0];
        out[1] = (float)loss[1];
        out[2] = (float)(0.5 * (loss[2] + loss[3]));
    }
}

// ======================= launch =======================
extern "C" void kernel_launch(void* const* d_in, const int* in_sizes, int n_in,
                              void* d_out, int out_size)
{
    const float* orig_feats     = (const float*)d_in[0];
    const float* orig_feats_pos = (const float*)d_in[1];
    const float* orig_code      = (const float*)d_in[4];
    const float* orig_code_pos  = (const float*)d_in[5];
    const float* coords1        = (const float*)d_in[8];
    const float* coords2        = (const float*)d_in[9];
    const int*   perms          = (const int*)d_in[10];
    float* out = (float*)d_out;

    zero_kernel<<<256, 256>>>();

    dim3 tb(32, 8);
    transpose_kernel<<<dim3(25, CF / 32, NB), tb>>>(orig_feats,     0, CF);
    transpose_kernel<<<dim3(25, CC / 32, NB), tb>>>(orig_code,      1, CC);
    transpose_kernel<<<dim3(25, CF / 32, NB), tb>>>(orig_feats_pos, 2, CF);
    transpose_kernel<<<dim3(25, CC / 32, NB), tb>>>(orig_code_pos,  3, CC);

    sample_norm_kernel<<<NB * NP, 256>>>(0, coords1, nullptr,    0, CF);
    sample_norm_kernel<<<NB * NP, 256>>>(1, coords1, nullptr,    1, CC);
    sample_norm_kernel<<<NB * NP, 256>>>(2, coords2, nullptr,    2, CF);
    sample_norm_kernel<<<NB * NP, 256>>>(3, coords2, nullptr,    3, CC);
    sample_norm_kernel<<<NB * NP, 256>>>(0, coords2, perms,      4, CF);
    sample_norm_kernel<<<NB * NP, 256>>>(1, coords2, perms,      5, CC);
    sample_norm_kernel<<<NB * NP, 256>>>(0, coords2, perms + NB, 6, CF);
    sample_norm_kernel<<<NB * NP, 256>>>(1, coords2, perms + NB, 7, CC);

    corr_mma_kernel<<<dim3(8, 8, 64), 512>>>();

    finalize_kernel<<<1, 256>>>(out);
}

// round 4
// speedup vs baseline: 5.9561x; 1.2003x over previous
#include <cuda_runtime.h>
#include <cuda_bf16.h>
#include <cstdint>
#include <math.h>

#define NB 16
#define NP 1024
#define CF 768
#define CC 512
#define HW 28
#define PIX 784
#define KT 32
#define STR 40            // padded smem k-stride (elements)

// ======================= scratch (device globals) =======================
__device__ __nv_bfloat16 g_Ftb [NB * PIX * CF];   // bf16 transposed (B,784,C)
__device__ __nv_bfloat16 g_Fptb[NB * PIX * CF];
__device__ __nv_bfloat16 g_Ctb [NB * PIX * CC];
__device__ __nv_bfloat16 g_Cptb[NB * PIX * CC];

__device__ __nv_bfloat16 g_F1 [NB * NP * CF];
__device__ __nv_bfloat16 g_C1 [NB * NP * CC];
__device__ __nv_bfloat16 g_F2p[NB * NP * CF];
__device__ __nv_bfloat16 g_C2p[NB * NP * CC];
__device__ __nv_bfloat16 g_Fn0[NB * NP * CF];
__device__ __nv_bfloat16 g_Cn0[NB * NP * CC];
__device__ __nv_bfloat16 g_Fn1[NB * NP * CF];
__device__ __nv_bfloat16 g_Cn1[NB * NP * CC];

__device__ float  g_rowfd[4 * NB * NP];
__device__ float  g_rowrc[4 * NB * NP];
__device__ double g_scal[4];

__device__ __forceinline__ __nv_bfloat16* tdst_ptr(int id) {
    switch (id) {
        case 0: return g_Ftb;  case 1: return g_Ctb;
        case 2: return g_Fptb; default: return g_Cptb;
    }
}

// ======================= zero =======================
__global__ void zero_kernel() {
    int i = blockIdx.x * 256 + threadIdx.x;
    if (i < 4 * NB * NP) { g_rowfd[i] = 0.f; g_rowrc[i] = 0.f; }
    if (i < 4) g_scal[i] = 0.0;
}

// ======================= transpose (B,C,784) fp32 -> (B,784,C) bf16 =======================
__global__ void __launch_bounds__(256) transpose_kernel(const float* __restrict__ in,
                                                        int dst_id, int C) {
    __nv_bfloat16* out = tdst_ptr(dst_id);
    __shared__ float t[64][33];
    int b  = blockIdx.z;
    int c0 = blockIdx.y * 64;
    int h0 = blockIdx.x * 32;
    int x = threadIdx.x, y = threadIdx.y;   // 32x8
    #pragma unroll
    for (int i = 0; i < 64; i += 8) {
        int c = c0 + y + i, h = h0 + x;
        if (h < PIX) t[y + i][x] = in[((size_t)b * C + c) * PIX + h];
    }
    __syncthreads();
    #pragma unroll
    for (int i = 0; i < 32; i += 8) {
        int h = h0 + y + i;
        if (h < PIX) {
            __nv_bfloat162 v = __floats2bfloat162_rn(t[2 * x][y + i], t[2 * x + 1][y + i]);
            *(__nv_bfloat162*)(out + ((size_t)b * PIX + h) * C + c0 + 2 * x) = v;
        }
    }
}

// ======================= fused bilinear sample + normalize =======================
// grid (NB*NP, 4). 160 threads: t<96 -> feats vec8, 96<=t<160 -> code vec8.
__global__ void __launch_bounds__(160) sample_all_kernel(
    const float* __restrict__ coords1,
    const float* __restrict__ coords2,
    const int*   __restrict__ perms)
{
    int bp = blockIdx.x;
    int g  = blockIdx.y;
    int b = bp >> 10, p = bp & 1023;

    const float* coords = (g == 0) ? coords1 : coords2;
    int bs = b;
    if (g == 2) bs = perms[b];
    else if (g == 3) bs = perms[NB + b];

    const __nv_bfloat16 *srcF, *srcC;
    __nv_bfloat16 *dstF, *dstC;
    switch (g) {
        case 0:  srcF = g_Ftb;  srcC = g_Ctb;  dstF = g_F1;  dstC = g_C1;  break;
        case 1:  srcF = g_Fptb; srcC = g_Cptb; dstF = g_F2p; dstC = g_C2p; break;
        case 2:  srcF = g_Ftb;  srcC = g_Ctb;  dstF = g_Fn0; dstC = g_Cn0; break;
        default: srcF = g_Ftb;  srcC = g_Ctb;  dstF = g_Fn1; dstC = g_Cn1; break;
    }

    float u = coords[(size_t)(b * NP + p) * 2 + 0];
    float v = coords[(size_t)(b * NP + p) * 2 + 1];
    float x = ((u * 2.f - 1.f) + 1.f) * 0.5f * (float)(HW - 1);
    float y = ((v * 2.f - 1.f) + 1.f) * 0.5f * (float)(HW - 1);
    float x0 = floorf(x), y0 = floorf(y);
    float wx = x - x0, wy = y - y0;
    int x0c = (int)fminf(fmaxf(x0,       0.f), (float)(HW - 1));
    int x1c = (int)fminf(fmaxf(x0 + 1.f, 0.f), (float)(HW - 1));
    int y0c = (int)fminf(fmaxf(y0,       0.f), (float)(HW - 1));
    int y1c = (int)fminf(fmaxf(y0 + 1.f, 0.f), (float)(HW - 1));
    float w00 = (1.f - wx) * (1.f - wy);
    float w01 = (1.f - wx) * wy;
    float w10 = wx * (1.f - wy);
    float w11 = wx * wy;
    int o00 = y0c * HW + x0c, o01 = y1c * HW + x0c;
    int o10 = y0c * HW + x1c, o11 = y1c * HW + x1c;

    int tid = threadIdx.x;
    bool isF = tid < 96;
    const __nv_bfloat16* S = isF ? srcF : srcC;
    int C  = isF ? CF : CC;
    int vx = isF ? tid : tid - 96;

    size_t rb = (size_t)bs * PIX;
    uint4 q00 = *(const uint4*)(S + (rb + o00) * C + vx * 8);
    uint4 q01 = *(const uint4*)(S + (rb + o01) * C + vx * 8);
    uint4 q10 = *(const uint4*)(S + (rb + o10) * C + vx * 8);
    uint4 q11 = *(const uint4*)(S + (rb + o11) * C + vx * 8);

    float2 vv[4] = {{0.f,0.f},{0.f,0.f},{0.f,0.f},{0.f,0.f}};
    auto addc = [&](uint4 q, float w) {
        uint32_t arr[4] = {q.x, q.y, q.z, q.w};
        #pragma unroll
        for (int k = 0; k < 4; k++) {
            float2 f = __bfloat1622float2(*(__nv_bfloat162*)&arr[k]);
            vv[k].x += w * f.x;
            vv[k].y += w * f.y;
        }
    };
    addc(q00, w00); addc(q01, w01); addc(q10, w10); addc(q11, w11);

    float ssq = 0.f;
    #pragma unroll
    for (int k = 0; k < 4; k++) ssq += vv[k].x * vv[k].x + vv[k].y * vv[k].y;

    #pragma unroll
    for (int off = 16; off; off >>= 1) ssq += __shfl_xor_sync(0xffffffffu, ssq, off);
    __shared__ float sred[5];
    if ((tid & 31) == 0) sred[tid >> 5] = ssq;
    __syncthreads();
    float sum = isF ? (sred[0] + sred[1] + sred[2]) : (sred[3] + sred[4]);
    float scale = 1.f / fmaxf(sqrtf(sum), 1e-10f);

    uint4 o;
    uint32_t* op = (uint32_t*)&o;
    #pragma unroll
    for (int k = 0; k < 4; k++) {
        __nv_bfloat162 h = __floats2bfloat162_rn(vv[k].x * scale, vv[k].y * scale);
        op[k] = *(uint32_t*)&h;
    }
    __nv_bfloat16* D = isF ? dstF : dstC;
    *(uint4*)(D + (size_t)(b * NP + p) * C + vx * 8) = o;
}

// ======================= HMMA correlation kernels =======================
__device__ __forceinline__ void mma_bf16(float (&d)[4], const uint32_t (&a)[4],
                                         uint32_t b0, uint32_t b1) {
    asm volatile(
        "mma.sync.aligned.m16n8k16.row.col.f32.bf16.bf16.f32 "
        "{%0,%1,%2,%3}, {%4,%5,%6,%7}, {%8,%9}, {%0,%1,%2,%3};\n"
        : "+f"(d[0]), "+f"(d[1]), "+f"(d[2]), "+f"(d[3])
        : "r"(a[0]), "r"(a[1]), "r"(a[2]), "r"(a[3]), "r"(b0), "r"(b1));
}

__device__ __forceinline__ void warp_mma_tile(
    const __nv_bfloat16* __restrict__ As, const __nv_bfloat16* __restrict__ Bs,
    int wm, int wn, int g, int t, float (&acc)[2][4][4])
{
    #pragma unroll
    for (int ks = 0; ks < 2; ks++) {
        int k0 = ks * 16 + 2 * t;
        uint32_t a[2][4];
        #pragma unroll
        for (int i = 0; i < 2; i++) {
            const __nv_bfloat16* base = As + (wm * 32 + i * 16 + g) * STR + k0;
            a[i][0] = *(const uint32_t*)(base);
            a[i][1] = *(const uint32_t*)(base + 8 * STR);
            a[i][2] = *(const uint32_t*)(base + 8);
            a[i][3] = *(const uint32_t*)(base + 8 * STR + 8);
        }
        #pragma unroll
        for (int j = 0; j < 4; j++) {
            const __nv_bfloat16* nb = Bs + (wn * 32 + j * 8 + g) * STR + k0;
            uint32_t b0 = *(const uint32_t*)(nb);
            uint32_t b1 = *(const uint32_t*)(nb + 8);
            #pragma unroll
            for (int i = 0; i < 2; i++)
                mma_bf16(acc[i][j], a[i], b0, b1);
        }
    }
}

#define NCH 40

// SYM=false: generic tile (4 slots; slot0 restricted to diagonal tiles).
// SYM=true : slot-0 strictly-upper tile; adds column sums + doubled scalar.
template <bool SYM>
__device__ __forceinline__ void corr_body(
    int slot, int b, int p0, int q0,
    const __nv_bfloat16* Af_r, const __nv_bfloat16* Ac_r,
    const __nv_bfloat16* Bf_r, const __nv_bfloat16* Bc_r)
{
    __shared__ __align__(16) __nv_bfloat16 smA[2][128 * STR];
    __shared__ __align__(16) __nv_bfloat16 smB[2][128 * STR];
    __shared__ float  red_f[128];
    __shared__ float  red_r[128];
    __shared__ float  red_cf[128];
    __shared__ float  red_cr[128];
    __shared__ double red_d[16];

    int tid = threadIdx.x;
    int wid = tid >> 5, lane = tid & 31;
    int g = lane >> 2, t = lane & 3;
    int wm = wid >> 2, wn = wid & 3;
    int lrow = tid >> 2, lseg = tid & 3;

    if (tid < 128) {
        red_f[tid] = 0.f; red_r[tid] = 0.f;
        if (SYM) { red_cf[tid] = 0.f; red_cr[tid] = 0.f; }
    }

    float facc[2][4][4] = {};
    float cacc[2][4][4] = {};

    auto load_src = [&](int c, uint4& ra, uint4& rb) {
        if (c < 24) {
            size_t off = (size_t)lrow * CF + c * KT + lseg * 8;
            ra = *(const uint4*)(Af_r + off);
            rb = *(const uint4*)(Bf_r + off);
        } else {
            size_t off = (size_t)lrow * CC + (c - 24) * KT + lseg * 8;
            ra = *(const uint4*)(Ac_r + off);
            rb = *(const uint4*)(Bc_r + off);
        }
    };

    uint4 ra, rb;
    load_src(0, ra, rb);
    *(uint4*)&smA[0][lrow * STR + lseg * 8] = ra;
    *(uint4*)&smB[0][lrow * STR + lseg * 8] = rb;
    __syncthreads();

    for (int c = 0; c < NCH; c++) {
        int buf = c & 1;
        if (c + 1 < NCH) load_src(c + 1, ra, rb);
        if (c < 24) warp_mma_tile(smA[buf], smB[buf], wm, wn, g, t, facc);
        else        warp_mma_tile(smA[buf], smB[buf], wm, wn, g, t, cacc);
        if (c + 1 < NCH) {
            int nb = (c + 1) & 1;
            *(uint4*)&smA[nb][lrow * STR + lseg * 8] = ra;
            *(uint4*)&smB[nb][lrow * STR + lseg * 8] = rb;
        }
        __syncthreads();
    }

    // -------- epilogue --------
    float lsum = 0.f;
    float rf[2][2] = {}, rr[2][2] = {};
    float cf0[4] = {}, cf1[4] = {}, cr0[4] = {}, cr1[4] = {};
    #pragma unroll
    for (int i = 0; i < 2; i++) {
        #pragma unroll
        for (int j = 0; j < 4; j++) {
            float f0 = facc[i][j][0], f1 = facc[i][j][1];
            float f2 = facc[i][j][2], f3 = facc[i][j][3];
            float r0 = fmaxf(cacc[i][j][0], 0.f), r1 = fmaxf(cacc[i][j][1], 0.f);
            float r2 = fmaxf(cacc[i][j][2], 0.f), r3 = fmaxf(cacc[i][j][3], 0.f);
            rf[i][0] += f0 + f1;  rf[i][1] += f2 + f3;
            rr[i][0] += r0 + r1;  rr[i][1] += r2 + r3;
            if (SYM) {
                cf0[j] += f0 + f2;  cf1[j] += f1 + f3;
                cr0[j] += r0 + r2;  cr1[j] += r1 + r3;
            }
            lsum += r0 * f0 + r1 * f1 + r2 * f2 + r3 * f3;
        }
    }
    #pragma unroll
    for (int off = 1; off < 4; off <<= 1) {
        #pragma unroll
        for (int i = 0; i < 2; i++) {
            rf[i][0] += __shfl_xor_sync(0xffffffffu, rf[i][0], off);
            rf[i][1] += __shfl_xor_sync(0xffffffffu, rf[i][1], off);
            rr[i][0] += __shfl_xor_sync(0xffffffffu, rr[i][0], off);
            rr[i][1] += __shfl_xor_sync(0xffffffffu, rr[i][1], off);
        }
    }
    if (t == 0) {
        #pragma unroll
        for (int i = 0; i < 2; i++) {
            int r0i = wm * 32 + i * 16 + g;
            atomicAdd(&red_f[r0i],     rf[i][0]);
            atomicAdd(&red_f[r0i + 8], rf[i][1]);
            atomicAdd(&red_r[r0i],     rr[i][0]);
            atomicAdd(&red_r[r0i + 8], rr[i][1]);
        }
    }
    if (SYM) {
        // reduce col partials over the 8 g-lanes (stride-4 lanes)
        #pragma unroll
        for (int off = 4; off < 32; off <<= 1) {
            #pragma unroll
            for (int j = 0; j < 4; j++) {
                cf0[j] += __shfl_xor_sync(0xffffffffu, cf0[j], off);
                cf1[j] += __shfl_xor_sync(0xffffffffu, cf1[j], off);
                cr0[j] += __shfl_xor_sync(0xffffffffu, cr0[j], off);
                cr1[j] += __shfl_xor_sync(0xffffffffu, cr1[j], off);
            }
        }
        if (g == 0) {
            #pragma unroll
            for (int j = 0; j < 4; j++) {
                int c0i = wn * 32 + j * 8 + 2 * t;
                atomicAdd(&red_cf[c0i],     cf0[j]);
                atomicAdd(&red_cf[c0i + 1], cf1[j]);
                atomicAdd(&red_cr[c0i],     cr0[j]);
                atomicAdd(&red_cr[c0i + 1], cr1[j]);
            }
        }
    }
    #pragma unroll
    for (int off = 16; off; off >>= 1) lsum += __shfl_xor_sync(0xffffffffu, lsum, off);
    if (lane == 0) red_d[wid] = (double)lsum;
    __syncthreads();

    if (tid == 0) {
        double s = 0.0;
        #pragma unroll
        for (int w = 0; w < 16; w++) s += red_d[w];
        atomicAdd(&g_scal[slot], SYM ? 2.0 * s : s);
    }
    if (tid < 128) {
        int gi = slot * NB * NP + b * NP + p0 + tid;
        atomicAdd(&g_rowfd[gi], red_f[tid]);
        atomicAdd(&g_rowrc[gi], red_r[tid]);
        if (SYM) {
            int gj = slot * NB * NP + b * NP + q0 + tid;
            atomicAdd(&g_rowfd[gj], red_cf[tid]);
            atomicAdd(&g_rowrc[gj], red_cr[tid]);
        }
    }
}

__global__ void __launch_bounds__(512, 1) corr_mma_kernel()
{
    int slot = blockIdx.z >> 4;
    int b    = blockIdx.z & 15;
    if (slot == 0 && blockIdx.x != blockIdx.y) return;   // off-diag handled by sym kernel
    int p0 = blockIdx.y * 128;
    int q0 = blockIdx.x * 128;

    const __nv_bfloat16 *Bf, *Bc;
    switch (slot) {
        case 0:  Bf = g_F1;  Bc = g_C1;  break;
        case 1:  Bf = g_F2p; Bc = g_C2p; break;
        case 2:  Bf = g_Fn0; Bc = g_Cn0; break;
        default: Bf = g_Fn1; Bc = g_Cn1; break;
    }
    corr_body<false>(slot, b, p0, q0,
                     g_F1 + (size_t)(b * NP + p0) * CF,
                     g_C1 + (size_t)(b * NP + p0) * CC,
                     Bf   + (size_t)(b * NP + q0) * CF,
                     Bc   + (size_t)(b * NP + q0) * CC);
}

__device__ const int8_t PAIR_P[28] = {0,0,0,0,0,0,0, 1,1,1,1,1,1, 2,2,2,2,2, 3,3,3,3, 4,4,4, 5,5, 6};
__device__ const int8_t PAIR_Q[28] = {1,2,3,4,5,6,7, 2,3,4,5,6,7, 3,4,5,6,7, 4,5,6,7, 5,6,7, 6,7, 7};

__global__ void __launch_bounds__(512, 1) corr_sym_kernel()
{
    int b  = blockIdx.z;
    int p0 = (int)PAIR_P[blockIdx.x] * 128;
    int q0 = (int)PAIR_Q[blockIdx.x] * 128;
    corr_body<true>(0, b, p0, q0,
                    g_F1 + (size_t)(b * NP + p0) * CF,
                    g_C1 + (size_t)(b * NP + p0) * CC,
                    g_F1 + (size_t)(b * NP + q0) * CF,
                    g_C1 + (size_t)(b * NP + q0) * CC);
}

// ======================= finalize =======================
__global__ void finalize_kernel(float* out)
{
    __shared__ double sred[3][8];
    __shared__ double res[4][3];
    int tid = threadIdx.x;
    for (int s = 0; s < 4; s++) {
        double tf = 0.0, tr = 0.0, cx = 0.0;
        const float* rf = g_rowfd + s * NB * NP;
        const float* rr = g_rowrc + s * NB * NP;
        for (int i = tid; i < NB * NP; i += 256) {
            double f = (double)rf[i], r = (double)rr[i];
            tf += f; tr += r; cx += f * r;
        }
        #pragma unroll
        for (int off = 16; off; off >>= 1) {
            tf += __shfl_xor_sync(0xffffffffu, tf, off);
            tr += __shfl_xor_sync(0xffffffffu, tr, off);
            cx += __shfl_xor_sync(0xffffffffu, cx, off);
        }
        if ((tid & 31) == 0) { sred[0][tid >> 5] = tf; sred[1][tid >> 5] = tr; sred[2][tid >> 5] = cx; }
        __syncthreads();
        if (tid < 8) {
            double a = sred[0][tid], bv = sred[1][tid], c = sred[2][tid];
            #pragma unroll
            for (int off = 4; off; off >>= 1) {
                a  += __shfl_xor_sync(0xffu, a,  off);
                bv += __shfl_xor_sync(0xffu, bv, off);
                c  += __shfl_xor_sync(0xffu, c,  off);
            }
            if (tid == 0) { res[s][0] = a; res[s][1] = bv; res[s][2] = c; }
        }
        __syncthreads();
    }
    if (tid == 0) {
        const double BPQ = (double)NB * (double)NP * (double)NP;
        const double Q   = (double)NP;
        const double shifts[4] = {0.18, 0.12, 0.46, 0.46};
        double loss[4];
        for (int s = 0; s < 4; s++) {
            double tf = res[s][0], tr = res[s][1], cx = res[s][2];
            double A  = g_scal[s];
            double gm = tf / BPQ;
            loss[s] = (-A + cx / Q) / BPQ - (gm - shifts[s]) * (tr / BPQ);
        }
        out[0] = (float)loss[0];
        out[1] = (float)loss[1];
        out[2] = (float)(0.5 * (loss[2] + loss[3]));
    }
}

// ======================= launch =======================
extern "C" void kernel_launch(void* const* d_in, const int* in_sizes, int n_in,
                              void* d_out, int out_size)
{
    const float* orig_feats     = (const float*)d_in[0];
    const float* orig_feats_pos = (const float*)d_in[1];
    const float* orig_code      = (const float*)d_in[4];
    const float* orig_code_pos  = (const float*)d_in[5];
    const float* coords1        = (const float*)d_in[8];
    const float* coords2        = (const float*)d_in[9];
    const int*   perms          = (const int*)d_in[10];
    float* out = (float*)d_out;

    zero_kernel<<<256, 256>>>();

    dim3 tb(32, 8);
    transpose_kernel<<<dim3(25, CF / 64, NB), tb>>>(orig_feats,     0, CF);
    transpose_kernel<<<dim3(25, CC / 64, NB), tb>>>(orig_code,      1, CC);
    transpose_kernel<<<dim3(25, CF / 64, NB), tb>>>(orig_feats_pos, 2, CF);
    transpose_kernel<<<dim3(25, CC / 64, NB), tb>>>(orig_code_pos,  3, CC);

    sample_all_kernel<<<dim3(NB * NP, 4), 160>>>(coords1, coords2, perms);

    corr_mma_kernel<<<dim3(8, 8, 64), 512>>>();
    corr_sym_kernel<<<dim3(28, 1, 16), 512>>>();

    finalize_kernel<<<1, 256>>>(out);
}

// round 5
// speedup vs baseline: 6.0612x; 1.0176x over previous
#include <cuda_runtime.h>
#include <cuda_bf16.h>
#include <cstdint>
#include <math.h>

#define NB 16
#define NP 1024
#define CF 768
#define CC 512
#define HW 28
#define PIX 784
#define KT 32
#define STR 40            // padded smem k-stride (elements); 80B rows -> LDSM conflict-free

// ======================= scratch (device globals) =======================
__device__ __nv_bfloat16 g_Ftb [NB * PIX * CF];
__device__ __nv_bfloat16 g_Fptb[NB * PIX * CF];
__device__ __nv_bfloat16 g_Ctb [NB * PIX * CC];
__device__ __nv_bfloat16 g_Cptb[NB * PIX * CC];

__device__ __nv_bfloat16 g_F1 [NB * NP * CF];
__device__ __nv_bfloat16 g_C1 [NB * NP * CC];
__device__ __nv_bfloat16 g_F2p[NB * NP * CF];
__device__ __nv_bfloat16 g_C2p[NB * NP * CC];
__device__ __nv_bfloat16 g_Fn0[NB * NP * CF];
__device__ __nv_bfloat16 g_Cn0[NB * NP * CC];
__device__ __nv_bfloat16 g_Fn1[NB * NP * CF];
__device__ __nv_bfloat16 g_Cn1[NB * NP * CC];

__device__ float  g_rowfd[4 * NB * NP];
__device__ float  g_rowrc[4 * NB * NP];
__device__ double g_scal[4];

__device__ __forceinline__ __nv_bfloat16* tdst_ptr(int id) {
    switch (id) {
        case 0: return g_Ftb;  case 1: return g_Ctb;
        case 2: return g_Fptb; default: return g_Cptb;
    }
}

__device__ __forceinline__ uint32_t smem_u32(const void* p) {
    uint32_t a;
    asm("{ .reg .u64 t; cvta.to.shared.u64 t, %1; cvt.u32.u64 %0, t; }" : "=r"(a) : "l"(p));
    return a;
}
#define LDSM_X4(r0, r1, r2, r3, addr) \
    asm volatile("ldmatrix.sync.aligned.m8n8.x4.shared.b16 {%0,%1,%2,%3}, [%4];" \
                 : "=r"(r0), "=r"(r1), "=r"(r2), "=r"(r3) : "r"(addr))

// ======================= zero =======================
__global__ void zero_kernel() {
    int i = blockIdx.x * 256 + threadIdx.x;
    if (i < 4 * NB * NP) { g_rowfd[i] = 0.f; g_rowrc[i] = 0.f; }
    if (i < 4) g_scal[i] = 0.0;
}

// ======================= transpose (B,C,784) fp32 -> (B,784,C) bf16 =======================
__global__ void __launch_bounds__(256) transpose_kernel(const float* __restrict__ in,
                                                        int dst_id, int C) {
    __nv_bfloat16* out = tdst_ptr(dst_id);
    __shared__ float t[64][33];
    int b  = blockIdx.z;
    int c0 = blockIdx.y * 64;
    int h0 = blockIdx.x * 32;
    int x = threadIdx.x, y = threadIdx.y;   // 32x8
    #pragma unroll
    for (int i = 0; i < 64; i += 8) {
        int c = c0 + y + i, h = h0 + x;
        if (h < PIX) t[y + i][x] = in[((size_t)b * C + c) * PIX + h];
    }
    __syncthreads();
    #pragma unroll
    for (int i = 0; i < 32; i += 8) {
        int h = h0 + y + i;
        if (h < PIX) {
            __nv_bfloat162 v = __floats2bfloat162_rn(t[2 * x][y + i], t[2 * x + 1][y + i]);
            *(__nv_bfloat162*)(out + ((size_t)b * PIX + h) * C + c0 + 2 * x) = v;
        }
    }
}

// ======================= fused bilinear sample + normalize =======================
__global__ void __launch_bounds__(160) sample_all_kernel(
    const float* __restrict__ coords1,
    const float* __restrict__ coords2,
    const int*   __restrict__ perms)
{
    int bp = blockIdx.x;
    int g  = blockIdx.y;
    int b = bp >> 10, p = bp & 1023;

    const float* coords = (g == 0) ? coords1 : coords2;
    int bs = b;
    if (g == 2) bs = perms[b];
    else if (g == 3) bs = perms[NB + b];

    const __nv_bfloat16 *srcF, *srcC;
    __nv_bfloat16 *dstF, *dstC;
    switch (g) {
        case 0:  srcF = g_Ftb;  srcC = g_Ctb;  dstF = g_F1;  dstC = g_C1;  break;
        case 1:  srcF = g_Fptb; srcC = g_Cptb; dstF = g_F2p; dstC = g_C2p; break;
        case 2:  srcF = g_Ftb;  srcC = g_Ctb;  dstF = g_Fn0; dstC = g_Cn0; break;
        default: srcF = g_Ftb;  srcC = g_Ctb;  dstF = g_Fn1; dstC = g_Cn1; break;
    }

    float u = coords[(size_t)(b * NP + p) * 2 + 0];
    float v = coords[(size_t)(b * NP + p) * 2 + 1];
    float x = ((u * 2.f - 1.f) + 1.f) * 0.5f * (float)(HW - 1);
    float y = ((v * 2.f - 1.f) + 1.f) * 0.5f * (float)(HW - 1);
    float x0 = floorf(x), y0 = floorf(y);
    float wx = x - x0, wy = y - y0;
    int x0c = (int)fminf(fmaxf(x0,       0.f), (float)(HW - 1));
    int x1c = (int)fminf(fmaxf(x0 + 1.f, 0.f), (float)(HW - 1));
    int y0c = (int)fminf(fmaxf(y0,       0.f), (float)(HW - 1));
    int y1c = (int)fminf(fmaxf(y0 + 1.f, 0.f), (float)(HW - 1));
    float w00 = (1.f - wx) * (1.f - wy);
    float w01 = (1.f - wx) * wy;
    float w10 = wx * (1.f - wy);
    float w11 = wx * wy;
    int o00 = y0c * HW + x0c, o01 = y1c * HW + x0c;
    int o10 = y0c * HW + x1c, o11 = y1c * HW + x1c;

    int tid = threadIdx.x;
    bool isF = tid < 96;
    const __nv_bfloat16* S = isF ? srcF : srcC;
    int C  = isF ? CF : CC;
    int vx = isF ? tid : tid - 96;

    size_t rb = (size_t)bs * PIX;
    uint4 q00 = *(const uint4*)(S + (rb + o00) * C + vx * 8);
    uint4 q01 = *(const uint4*)(S + (rb + o01) * C + vx * 8);
    uint4 q10 = *(const uint4*)(S + (rb + o10) * C + vx * 8);
    uint4 q11 = *(const uint4*)(S + (rb + o11) * C + vx * 8);

    float2 vv[4] = {{0.f,0.f},{0.f,0.f},{0.f,0.f},{0.f,0.f}};
    auto addc = [&](uint4 q, float w) {
        uint32_t arr[4] = {q.x, q.y, q.z, q.w};
        #pragma unroll
        for (int k = 0; k < 4; k++) {
            float2 f = __bfloat1622float2(*(__nv_bfloat162*)&arr[k]);
            vv[k].x += w * f.x;
            vv[k].y += w * f.y;
        }
    };
    addc(q00, w00); addc(q01, w01); addc(q10, w10); addc(q11, w11);

    float ssq = 0.f;
    #pragma unroll
    for (int k = 0; k < 4; k++) ssq += vv[k].x * vv[k].x + vv[k].y * vv[k].y;

    #pragma unroll
    for (int off = 16; off; off >>= 1) ssq += __shfl_xor_sync(0xffffffffu, ssq, off);
    __shared__ float sred[5];
    if ((tid & 31) == 0) sred[tid >> 5] = ssq;
    __syncthreads();
    float sum = isF ? (sred[0] + sred[1] + sred[2]) : (sred[3] + sred[4]);
    float scale = 1.f / fmaxf(sqrtf(sum), 1e-10f);

    uint4 o;
    uint32_t* op = (uint32_t*)&o;
    #pragma unroll
    for (int k = 0; k < 4; k++) {
        __nv_bfloat162 h = __floats2bfloat162_rn(vv[k].x * scale, vv[k].y * scale);
        op[k] = *(uint32_t*)&h;
    }
    __nv_bfloat16* D = isF ? dstF : dstC;
    *(uint4*)(D + (size_t)(b * NP + p) * C + vx * 8) = o;
}

// ======================= HMMA correlation kernels =======================
__device__ __forceinline__ void mma_bf16(float (&d)[4], const uint32_t (&a)[4],
                                         uint32_t b0, uint32_t b1) {
    asm volatile(
        "mma.sync.aligned.m16n8k16.row.col.f32.bf16.bf16.f32 "
        "{%0,%1,%2,%3}, {%4,%5,%6,%7}, {%8,%9}, {%0,%1,%2,%3};\n"
        : "+f"(d[0]), "+f"(d[1]), "+f"(d[2]), "+f"(d[3])
        : "r"(a[0]), "r"(a[1]), "r"(a[2]), "r"(a[3]), "r"(b0), "r"(b1));
}

// A-fragment LDSM address (per thread, element offset within tile buffer):
//   (wm*32 + (lane&15))*STR + (lane>>4)*8   [+ i*16*STR + ks*16]
// B-fragment LDSM address:
//   (wn*32 + ((lane>>4)&1)*8 + (lane&7))*STR + ((lane>>3)&1)*8   [+ jp*16*STR + ks*16]
__device__ __forceinline__ void warp_mma_tile_ldsm(
    uint32_t smA, uint32_t smB, uint32_t aoff, uint32_t boff, float (&acc)[2][4][4])
{
    #pragma unroll
    for (int ks = 0; ks < 2; ks++) {
        uint32_t a[2][4];
        #pragma unroll
        for (int i = 0; i < 2; i++) {
            uint32_t addr = smA + 2u * (aoff + i * 16 * STR + ks * 16);
            LDSM_X4(a[i][0], a[i][1], a[i][2], a[i][3], addr);
        }
        #pragma unroll
        for (int jp = 0; jp < 2; jp++) {
            uint32_t baddr = smB + 2u * (boff + jp * 16 * STR + ks * 16);
            uint32_t b0, b1, b2, b3;
            LDSM_X4(b0, b1, b2, b3, baddr);
            #pragma unroll
            for (int i = 0; i < 2; i++) {
                mma_bf16(acc[i][jp * 2 + 0], a[i], b0, b1);
                mma_bf16(acc[i][jp * 2 + 1], a[i], b2, b3);
            }
        }
    }
}

#define NCH 40

template <bool SYM>
__device__ __forceinline__ void corr_body(
    int slot, int b, int p0, int q0,
    const __nv_bfloat16* Af_r, const __nv_bfloat16* Ac_r,
    const __nv_bfloat16* Bf_r, const __nv_bfloat16* Bc_r)
{
    __shared__ __align__(16) __nv_bfloat16 smA[2][128 * STR];
    __shared__ __align__(16) __nv_bfloat16 smB[2][128 * STR];
    __shared__ float  red_f[128];
    __shared__ float  red_r[128];
    __shared__ float  red_cf[128];
    __shared__ float  red_cr[128];
    __shared__ double red_d[16];

    int tid = threadIdx.x;
    int wid = tid >> 5, lane = tid & 31;
    int g = lane >> 2, t = lane & 3;
    int wm = wid >> 2, wn = wid & 3;
    int lrow = tid >> 2, lseg = tid & 3;

    uint32_t smA_u[2] = { smem_u32(&smA[0][0]), smem_u32(&smA[1][0]) };
    uint32_t smB_u[2] = { smem_u32(&smB[0][0]), smem_u32(&smB[1][0]) };
    uint32_t aoff = (uint32_t)((wm * 32 + (lane & 15)) * STR + (lane >> 4) * 8);
    uint32_t boff = (uint32_t)((wn * 32 + ((lane >> 4) & 1) * 8 + (lane & 7)) * STR + ((lane >> 3) & 1) * 8);

    if (tid < 128) {
        red_f[tid] = 0.f; red_r[tid] = 0.f;
        if (SYM) { red_cf[tid] = 0.f; red_cr[tid] = 0.f; }
    }

    float facc[2][4][4] = {};
    float cacc[2][4][4] = {};

    auto load_src = [&](int c, uint4& ra, uint4& rb) {
        if (c < 24) {
            size_t off = (size_t)lrow * CF + c * KT + lseg * 8;
            ra = *(const uint4*)(Af_r + off);
            rb = *(const uint4*)(Bf_r + off);
        } else {
            size_t off = (size_t)lrow * CC + (c - 24) * KT + lseg * 8;
            ra = *(const uint4*)(Ac_r + off);
            rb = *(const uint4*)(Bc_r + off);
        }
    };

    uint4 ra, rb;
    load_src(0, ra, rb);
    *(uint4*)&smA[0][lrow * STR + lseg * 8] = ra;
    *(uint4*)&smB[0][lrow * STR + lseg * 8] = rb;
    __syncthreads();

    for (int c = 0; c < NCH; c++) {
        int buf = c & 1;
        if (c + 1 < NCH) load_src(c + 1, ra, rb);
        if (c < 24) warp_mma_tile_ldsm(smA_u[buf], smB_u[buf], aoff, boff, facc);
        else        warp_mma_tile_ldsm(smA_u[buf], smB_u[buf], aoff, boff, cacc);
        if (c + 1 < NCH) {
            int nb = (c + 1) & 1;
            *(uint4*)&smA[nb][lrow * STR + lseg * 8] = ra;
            *(uint4*)&smB[nb][lrow * STR + lseg * 8] = rb;
        }
        __syncthreads();
    }

    // -------- epilogue --------
    float lsum = 0.f;
    float rf[2][2] = {}, rr[2][2] = {};
    float cf0[4] = {}, cf1[4] = {}, cr0[4] = {}, cr1[4] = {};
    #pragma unroll
    for (int i = 0; i < 2; i++) {
        #pragma unroll
        for (int j = 0; j < 4; j++) {
            float f0 = facc[i][j][0], f1 = facc[i][j][1];
            float f2 = facc[i][j][2], f3 = facc[i][j][3];
            float r0 = fmaxf(cacc[i][j][0], 0.f), r1 = fmaxf(cacc[i][j][1], 0.f);
            float r2 = fmaxf(cacc[i][j][2], 0.f), r3 = fmaxf(cacc[i][j][3], 0.f);
            rf[i][0] += f0 + f1;  rf[i][1] += f2 + f3;
            rr[i][0] += r0 + r1;  rr[i][1] += r2 + r3;
            if (SYM) {
                cf0[j] += f0 + f2;  cf1[j] += f1 + f3;
                cr0[j] += r0 + r2;  cr1[j] += r1 + r3;
            }
            lsum += r0 * f0 + r1 * f1 + r2 * f2 + r3 * f3;
        }
    }
    #pragma unroll
    for (int off = 1; off < 4; off <<= 1) {
        #pragma unroll
        for (int i = 0; i < 2; i++) {
            rf[i][0] += __shfl_xor_sync(0xffffffffu, rf[i][0], off);
            rf[i][1] += __shfl_xor_sync(0xffffffffu, rf[i][1], off);
            rr[i][0] += __shfl_xor_sync(0xffffffffu, rr[i][0], off);
            rr[i][1] += __shfl_xor_sync(0xffffffffu, rr[i][1], off);
        }
    }
    if (t == 0) {
        #pragma unroll
        for (int i = 0; i < 2; i++) {
            int r0i = wm * 32 + i * 16 + g;
            atomicAdd(&red_f[r0i],     rf[i][0]);
            atomicAdd(&red_f[r0i + 8], rf[i][1]);
            atomicAdd(&red_r[r0i],     rr[i][0]);
            atomicAdd(&red_r[r0i + 8], rr[i][1]);
        }
    }
    if (SYM) {
        #pragma unroll
        for (int off = 4; off < 32; off <<= 1) {
            #pragma unroll
            for (int j = 0; j < 4; j++) {
                cf0[j] += __shfl_xor_sync(0xffffffffu, cf0[j], off);
                cf1[j] += __shfl_xor_sync(0xffffffffu, cf1[j], off);
                cr0[j] += __shfl_xor_sync(0xffffffffu, cr0[j], off);
                cr1[j] += __shfl_xor_sync(0xffffffffu, cr1[j], off);
            }
        }
        if (g == 0) {
            #pragma unroll
            for (int j = 0; j < 4; j++) {
                int c0i = wn * 32 + j * 8 + 2 * t;
                atomicAdd(&red_cf[c0i],     cf0[j]);
                atomicAdd(&red_cf[c0i + 1], cf1[j]);
                atomicAdd(&red_cr[c0i],     cr0[j]);
                atomicAdd(&red_cr[c0i + 1], cr1[j]);
            }
        }
    }
    #pragma unroll
    for (int off = 16; off; off >>= 1) lsum += __shfl_xor_sync(0xffffffffu, lsum, off);
    if (lane == 0) red_d[wid] = (double)lsum;
    __syncthreads();

    if (tid == 0) {
        double s = 0.0;
        #pragma unroll
        for (int w = 0; w < 16; w++) s += red_d[w];
        atomicAdd(&g_scal[slot], SYM ? 2.0 * s : s);
    }
    if (tid < 128) {
        int gi = slot * NB * NP + b * NP + p0 + tid;
        atomicAdd(&g_rowfd[gi], red_f[tid]);
        atomicAdd(&g_rowrc[gi], red_r[tid]);
        if (SYM) {
            int gj = slot * NB * NP + b * NP + q0 + tid;
            atomicAdd(&g_rowfd[gj], red_cf[tid]);
            atomicAdd(&g_rowrc[gj], red_cr[tid]);
        }
    }
}

// slots 1..3 full 8x8 tiling
__global__ void __launch_bounds__(512, 1) corr_mma_kernel()
{
    int slot = 1 + (blockIdx.z >> 4);
    int b    = blockIdx.z & 15;
    int p0   = blockIdx.y * 128;
    int q0   = blockIdx.x * 128;

    const __nv_bfloat16 *Bf, *Bc;
    switch (slot) {
        case 1:  Bf = g_F2p; Bc = g_C2p; break;
        case 2:  Bf = g_Fn0; Bc = g_Cn0; break;
        default: Bf = g_Fn1; Bc = g_Cn1; break;
    }
    corr_body<false>(slot, b, p0, q0,
                     g_F1 + (size_t)(b * NP + p0) * CF,
                     g_C1 + (size_t)(b * NP + p0) * CC,
                     Bf   + (size_t)(b * NP + q0) * CF,
                     Bc   + (size_t)(b * NP + q0) * CC);
}

// slot 0: x<28 -> strictly-upper pairs (symmetric), x>=28 -> diagonal tiles
__device__ const int8_t PAIR_P[36] = {0,0,0,0,0,0,0, 1,1,1,1,1,1, 2,2,2,2,2, 3,3,3,3, 4,4,4, 5,5, 6, 0,1,2,3,4,5,6,7};
__device__ const int8_t PAIR_Q[36] = {1,2,3,4,5,6,7, 2,3,4,5,6,7, 3,4,5,6,7, 4,5,6,7, 5,6,7, 6,7, 7, 0,1,2,3,4,5,6,7};

__global__ void __launch_bounds__(512, 1) corr_sym_kernel()
{
    int b  = blockIdx.z;
    int p0 = (int)PAIR_P[blockIdx.x] * 128;
    int q0 = (int)PAIR_Q[blockIdx.x] * 128;
    const __nv_bfloat16* Af = g_F1 + (size_t)(b * NP + p0) * CF;
    const __nv_bfloat16* Ac = g_C1 + (size_t)(b * NP + p0) * CC;
    const __nv_bfloat16* Bf = g_F1 + (size_t)(b * NP + q0) * CF;
    const __nv_bfloat16* Bc = g_C1 + (size_t)(b * NP + q0) * CC;
    if (blockIdx.x < 28) corr_body<true >(0, b, p0, q0, Af, Ac, Bf, Bc);
    else                 corr_body<false>(0, b, p0, q0, Af, Ac, Bf, Bc);
}

// ======================= finalize =======================
__global__ void finalize_kernel(float* out)
{
    __shared__ double sred[3][8];
    __shared__ double res[4][3];
    int tid = threadIdx.x;
    for (int s = 0; s < 4; s++) {
        double tf = 0.0, tr = 0.0, cx = 0.0;
        const float* rf = g_rowfd + s * NB * NP;
        const float* rr = g_rowrc + s * NB * NP;
        for (int i = tid; i < NB * NP; i += 256) {
            double f = (double)rf[i], r = (double)rr[i];
            tf += f; tr += r; cx += f * r;
        }
        #pragma unroll
        for (int off = 16; off; off >>= 1) {
            tf += __shfl_xor_sync(0xffffffffu, tf, off);
            tr += __shfl_xor_sync(0xffffffffu, tr, off);
            cx += __shfl_xor_sync(0xffffffffu, cx, off);
        }
        if ((tid & 31) == 0) { sred[0][tid >> 5] = tf; sred[1][tid >> 5] = tr; sred[2][tid >> 5] = cx; }
        __syncthreads();
        if (tid < 8) {
            double a = sred[0][tid], bv = sred[1][tid], c = sred[2][tid];
            #pragma unroll
            for (int off = 4; off; off >>= 1) {
                a  += __shfl_xor_sync(0xffu, a,  off);
                bv += __shfl_xor_sync(0xffu, bv, off);
                c  += __shfl_xor_sync(0xffu, c,  off);
            }
            if (tid == 0) { res[s][0] = a; res[s][1] = bv; res[s][2] = c; }
        }
        __syncthreads();
    }
    if (tid == 0) {
        const double BPQ = (double)NB * (double)NP * (double)NP;
        const double Q   = (double)NP;
        const double shifts[4] = {0.18, 0.12, 0.46, 0.46};
        double loss[4];
        for (int s = 0; s < 4; s++) {
            double tf = res[s][0], tr = res[s][1], cx = res[s][2];
            double A  = g_scal[s];
            double gm = tf / BPQ;
            loss[s] = (-A + cx / Q) / BPQ - (gm - shifts[s]) * (tr / BPQ);
        }
        out[0] = (float)loss[0];
        out[1] = (float)loss[1];
        out[2] = (float)(0.5 * (loss[2] + loss[3]));
    }
}

// ======================= launch =======================
extern "C" void kernel_launch(void* const* d_in, const int* in_sizes, int n_in,
                              void* d_out, int out_size)
{
    const float* orig_feats     = (const float*)d_in[0];
    const float* orig_feats_pos = (const float*)d_in[1];
    const float* orig_code      = (const float*)d_in[4];
    const float* orig_code_pos  = (const float*)d_in[5];
    const float* coords1        = (const float*)d_in[8];
    const float* coords2        = (const float*)d_in[9];
    const int*   perms          = (const int*)d_in[10];
    float* out = (float*)d_out;

    zero_kernel<<<256, 256>>>();

    dim3 tb(32, 8);
    transpose_kernel<<<dim3(25, CF / 64, NB), tb>>>(orig_feats,     0, CF);
    transpose_kernel<<<dim3(25, CC / 64, NB), tb>>>(orig_code,      1, CC);
    transpose_kernel<<<dim3(25, CF / 64, NB), tb>>>(orig_feats_pos, 2, CF);
    transpose_kernel<<<dim3(25, CC / 64, NB), tb>>>(orig_code_pos,  3, CC);

    sample_all_kernel<<<dim3(NB * NP, 4), 160>>>(coords1, coords2, perms);

    corr_mma_kernel<<<dim3(8, 8, 48), 512>>>();
    corr_sym_kernel<<<dim3(36, 1, 16), 512>>>();

    finalize_kernel<<<1, 256>>>(out);
}

// round 6
// speedup vs baseline: 6.5606x; 1.0824x over previous
#include <cuda_runtime.h>
#include <cuda_bf16.h>
#include <cstdint>
#include <math.h>

#define NB 16
#define NP 1024
#define CF 768
#define CC 512
#define HW 28
#define PIX 784
#define KT 32
#define STR 40            // padded smem k-stride (elements); 80B rows -> LDSM conflict-free
#define STAGES 4
#define BUF_ELE (128 * STR)                 // 5120 elements per (stage, matrix)
#define SMEM_BYTES (STAGES * 2 * BUF_ELE * 2)   // 81920

// ======================= scratch (device globals) =======================
__device__ __nv_bfloat16 g_Ftb [NB * PIX * CF];
__device__ __nv_bfloat16 g_Fptb[NB * PIX * CF];
__device__ __nv_bfloat16 g_Ctb [NB * PIX * CC];
__device__ __nv_bfloat16 g_Cptb[NB * PIX * CC];

__device__ __nv_bfloat16 g_F1 [NB * NP * CF];
__device__ __nv_bfloat16 g_C1 [NB * NP * CC];
__device__ __nv_bfloat16 g_F2p[NB * NP * CF];
__device__ __nv_bfloat16 g_C2p[NB * NP * CC];
__device__ __nv_bfloat16 g_Fn0[NB * NP * CF];
__device__ __nv_bfloat16 g_Cn0[NB * NP * CC];
__device__ __nv_bfloat16 g_Fn1[NB * NP * CF];
__device__ __nv_bfloat16 g_Cn1[NB * NP * CC];

__device__ float  g_rowfd[4 * NB * NP];
__device__ float  g_rowrc[4 * NB * NP];
__device__ double g_scal[4];

__device__ __forceinline__ __nv_bfloat16* tdst_ptr(int id) {
    switch (id) {
        case 0: return g_Ftb;  case 1: return g_Ctb;
        case 2: return g_Fptb; default: return g_Cptb;
    }
}

__device__ __forceinline__ uint32_t smem_u32(const void* p) {
    uint32_t a;
    asm("{ .reg .u64 t; cvta.to.shared.u64 t, %1; cvt.u32.u64 %0, t; }" : "=r"(a) : "l"(p));
    return a;
}
#define LDSM_X4(r0, r1, r2, r3, addr) \
    asm volatile("ldmatrix.sync.aligned.m8n8.x4.shared.b16 {%0,%1,%2,%3}, [%4];" \
                 : "=r"(r0), "=r"(r1), "=r"(r2), "=r"(r3) : "r"(addr))
#define CP_ASYNC_16(dst, src) \
    asm volatile("cp.async.cg.shared.global [%0], [%1], 16;" :: "r"(dst), "l"(src))
#define CP_COMMIT() asm volatile("cp.async.commit_group;" ::: "memory")
#define CP_WAIT2()  asm volatile("cp.async.wait_group 2;" ::: "memory")

// ======================= zero =======================
__global__ void zero_kernel() {
    int i = blockIdx.x * 256 + threadIdx.x;
    if (i < 4 * NB * NP) { g_rowfd[i] = 0.f; g_rowrc[i] = 0.f; }
    if (i < 4) g_scal[i] = 0.0;
}

// ======================= transpose (B,C,784) fp32 -> (B,784,C) bf16 =======================
__global__ void __launch_bounds__(256) transpose_kernel(const float* __restrict__ in,
                                                        int dst_id, int C) {
    __nv_bfloat16* out = tdst_ptr(dst_id);
    __shared__ float t[64][33];
    int b  = blockIdx.z;
    int c0 = blockIdx.y * 64;
    int h0 = blockIdx.x * 32;
    int x = threadIdx.x, y = threadIdx.y;   // 32x8
    #pragma unroll
    for (int i = 0; i < 64; i += 8) {
        int c = c0 + y + i, h = h0 + x;
        if (h < PIX) t[y + i][x] = in[((size_t)b * C + c) * PIX + h];
    }
    __syncthreads();
    #pragma unroll
    for (int i = 0; i < 32; i += 8) {
        int h = h0 + y + i;
        if (h < PIX) {
            __nv_bfloat162 v = __floats2bfloat162_rn(t[2 * x][y + i], t[2 * x + 1][y + i]);
            *(__nv_bfloat162*)(out + ((size_t)b * PIX + h) * C + c0 + 2 * x) = v;
        }
    }
}

// ======================= fused bilinear sample + normalize =======================
__global__ void __launch_bounds__(160) sample_all_kernel(
    const float* __restrict__ coords1,
    const float* __restrict__ coords2,
    const int*   __restrict__ perms)
{
    int bp = blockIdx.x;
    int g  = blockIdx.y;
    int b = bp >> 10, p = bp & 1023;

    const float* coords = (g == 0) ? coords1 : coords2;
    int bs = b;
    if (g == 2) bs = perms[b];
    else if (g == 3) bs = perms[NB + b];

    const __nv_bfloat16 *srcF, *srcC;
    __nv_bfloat16 *dstF, *dstC;
    switch (g) {
        case 0:  srcF = g_Ftb;  srcC = g_Ctb;  dstF = g_F1;  dstC = g_C1;  break;
        case 1:  srcF = g_Fptb; srcC = g_Cptb; dstF = g_F2p; dstC = g_C2p; break;
        case 2:  srcF = g_Ftb;  srcC = g_Ctb;  dstF = g_Fn0; dstC = g_Cn0; break;
        default: srcF = g_Ftb;  srcC = g_Ctb;  dstF = g_Fn1; dstC = g_Cn1; break;
    }

    float u = coords[(size_t)(b * NP + p) * 2 + 0];
    float v = coords[(size_t)(b * NP + p) * 2 + 1];
    float x = ((u * 2.f - 1.f) + 1.f) * 0.5f * (float)(HW - 1);
    float y = ((v * 2.f - 1.f) + 1.f) * 0.5f * (float)(HW - 1);
    float x0 = floorf(x), y0 = floorf(y);
    float wx = x - x0, wy = y - y0;
    int x0c = (int)fminf(fmaxf(x0,       0.f), (float)(HW - 1));
    int x1c = (int)fminf(fmaxf(x0 + 1.f, 0.f), (float)(HW - 1));
    int y0c = (int)fminf(fmaxf(y0,       0.f), (float)(HW - 1));
    int y1c = (int)fminf(fmaxf(y0 + 1.f, 0.f), (float)(HW - 1));
    float w00 = (1.f - wx) * (1.f - wy);
    float w01 = (1.f - wx) * wy;
    float w10 = wx * (1.f - wy);
    float w11 = wx * wy;
    int o00 = y0c * HW + x0c, o01 = y1c * HW + x0c;
    int o10 = y0c * HW + x1c, o11 = y1c * HW + x1c;

    int tid = threadIdx.x;
    bool isF = tid < 96;
    const __nv_bfloat16* S = isF ? srcF : srcC;
    int C  = isF ? CF : CC;
    int vx = isF ? tid : tid - 96;

    size_t rb = (size_t)bs * PIX;
    uint4 q00 = *(const uint4*)(S + (rb + o00) * C + vx * 8);
    uint4 q01 = *(const uint4*)(S + (rb + o01) * C + vx * 8);
    uint4 q10 = *(const uint4*)(S + (rb + o10) * C + vx * 8);
    uint4 q11 = *(const uint4*)(S + (rb + o11) * C + vx * 8);

    float2 vv[4] = {{0.f,0.f},{0.f,0.f},{0.f,0.f},{0.f,0.f}};
    auto addc = [&](uint4 q, float w) {
        uint32_t arr[4] = {q.x, q.y, q.z, q.w};
        #pragma unroll
        for (int k = 0; k < 4; k++) {
            float2 f = __bfloat1622float2(*(__nv_bfloat162*)&arr[k]);
            vv[k].x += w * f.x;
            vv[k].y += w * f.y;
        }
    };
    addc(q00, w00); addc(q01, w01); addc(q10, w10); addc(q11, w11);

    float ssq = 0.f;
    #pragma unroll
    for (int k = 0; k < 4; k++) ssq += vv[k].x * vv[k].x + vv[k].y * vv[k].y;

    #pragma unroll
    for (int off = 16; off; off >>= 1) ssq += __shfl_xor_sync(0xffffffffu, ssq, off);
    __shared__ float sred[5];
    if ((tid & 31) == 0) sred[tid >> 5] = ssq;
    __syncthreads();
    float sum = isF ? (sred[0] + sred[1] + sred[2]) : (sred[3] + sred[4]);
    float scale = 1.f / fmaxf(sqrtf(sum), 1e-10f);

    uint4 o;
    uint32_t* op = (uint32_t*)&o;
    #pragma unroll
    for (int k = 0; k < 4; k++) {
        __nv_bfloat162 h = __floats2bfloat162_rn(vv[k].x * scale, vv[k].y * scale);
        op[k] = *(uint32_t*)&h;
    }
    __nv_bfloat16* D = isF ? dstF : dstC;
    *(uint4*)(D + (size_t)(b * NP + p) * C + vx * 8) = o;
}

// ======================= HMMA correlation kernels =======================
__device__ __forceinline__ void mma_bf16(float (&d)[4], const uint32_t (&a)[4],
                                         uint32_t b0, uint32_t b1) {
    asm volatile(
        "mma.sync.aligned.m16n8k16.row.col.f32.bf16.bf16.f32 "
        "{%0,%1,%2,%3}, {%4,%5,%6,%7}, {%8,%9}, {%0,%1,%2,%3};\n"
        : "+f"(d[0]), "+f"(d[1]), "+f"(d[2]), "+f"(d[3])
        : "r"(a[0]), "r"(a[1]), "r"(a[2]), "r"(a[3]), "r"(b0), "r"(b1));
}

__device__ __forceinline__ void warp_mma_tile_ldsm(
    uint32_t smA, uint32_t smB, uint32_t aoff, uint32_t boff, float (&acc)[2][4][4])
{
    #pragma unroll
    for (int ks = 0; ks < 2; ks++) {
        uint32_t a[2][4];
        #pragma unroll
        for (int i = 0; i < 2; i++) {
            uint32_t addr = smA + 2u * (aoff + i * 16 * STR + ks * 16);
            LDSM_X4(a[i][0], a[i][1], a[i][2], a[i][3], addr);
        }
        #pragma unroll
        for (int jp = 0; jp < 2; jp++) {
            uint32_t baddr = smB + 2u * (boff + jp * 16 * STR + ks * 16);
            uint32_t b0, b1, b2, b3;
            LDSM_X4(b0, b1, b2, b3, baddr);
            #pragma unroll
            for (int i = 0; i < 2; i++) {
                mma_bf16(acc[i][jp * 2 + 0], a[i], b0, b1);
                mma_bf16(acc[i][jp * 2 + 1], a[i], b2, b3);
            }
        }
    }
}

#define NCH 40

template <bool SYM>
__device__ __forceinline__ void corr_body(
    int slot, int b, int p0, int q0,
    const __nv_bfloat16* Af_r, const __nv_bfloat16* Ac_r,
    const __nv_bfloat16* Bf_r, const __nv_bfloat16* Bc_r)
{
    extern __shared__ __align__(16) __nv_bfloat16 dynbuf[];   // [STAGES][2][BUF_ELE]
    __shared__ float  red_f[128];
    __shared__ float  red_r[128];
    __shared__ float  red_cf[128];
    __shared__ float  red_cr[128];
    __shared__ double red_d[16];

    int tid = threadIdx.x;
    int wid = tid >> 5, lane = tid & 31;
    int g = lane >> 2, t = lane & 3;
    int wm = wid >> 2, wn = wid & 3;
    int lrow = tid >> 2, lseg = tid & 3;

    uint32_t smem_base = smem_u32(dynbuf);
    uint32_t aoff = (uint32_t)((wm * 32 + (lane & 15)) * STR + (lane >> 4) * 8);
    uint32_t boff = (uint32_t)((wn * 32 + ((lane >> 4) & 1) * 8 + (lane & 7)) * STR + ((lane >> 3) & 1) * 8);
    uint32_t stoff = (uint32_t)(lrow * STR + lseg * 8) * 2u;   // byte offset within a buffer

    if (tid < 128) {
        red_f[tid] = 0.f; red_r[tid] = 0.f;
        if (SYM) { red_cf[tid] = 0.f; red_cr[tid] = 0.f; }
    }

    float facc[2][4][4] = {};
    float cacc[2][4][4] = {};

    auto issue_load = [&](int c) {
        int s = c & (STAGES - 1);
        uint32_t da = smem_base + (uint32_t)((s * 2 + 0) * BUF_ELE) * 2u + stoff;
        uint32_t db = smem_base + (uint32_t)((s * 2 + 1) * BUF_ELE) * 2u + stoff;
        const __nv_bfloat16 *pa, *pb;
        if (c < 24) {
            size_t off = (size_t)lrow * CF + c * KT + lseg * 8;
            pa = Af_r + off;  pb = Bf_r + off;
        } else {
            size_t off = (size_t)lrow * CC + (c - 24) * KT + lseg * 8;
            pa = Ac_r + off;  pb = Bc_r + off;
        }
        CP_ASYNC_16(da, pa);
        CP_ASYNC_16(db, pb);
        CP_COMMIT();
    };

    issue_load(0);
    issue_load(1);
    issue_load(2);

    for (int c = 0; c < NCH; c++) {
        CP_WAIT2();
        __syncthreads();
        if (c + 3 < NCH) issue_load(c + 3);
        int s = c & (STAGES - 1);
        uint32_t sa = smem_base + (uint32_t)((s * 2 + 0) * BUF_ELE) * 2u;
        uint32_t sb = smem_base + (uint32_t)((s * 2 + 1) * BUF_ELE) * 2u;
        if (c < 24) warp_mma_tile_ldsm(sa, sb, aoff, boff, facc);
        else        warp_mma_tile_ldsm(sa, sb, aoff, boff, cacc);
    }

    // -------- epilogue --------
    float lsum = 0.f;
    float rf[2][2] = {}, rr[2][2] = {};
    float cf0[4] = {}, cf1[4] = {}, cr0[4] = {}, cr1[4] = {};
    #pragma unroll
    for (int i = 0; i < 2; i++) {
        #pragma unroll
        for (int j = 0; j < 4; j++) {
            float f0 = facc[i][j][0], f1 = facc[i][j][1];
            float f2 = facc[i][j][2], f3 = facc[i][j][3];
            float r0 = fmaxf(cacc[i][j][0], 0.f), r1 = fmaxf(cacc[i][j][1], 0.f);
            float r2 = fmaxf(cacc[i][j][2], 0.f), r3 = fmaxf(cacc[i][j][3], 0.f);
            rf[i][0] += f0 + f1;  rf[i][1] += f2 + f3;
            rr[i][0] += r0 + r1;  rr[i][1] += r2 + r3;
            if (SYM) {
                cf0[j] += f0 + f2;  cf1[j] += f1 + f3;
                cr0[j] += r0 + r2;  cr1[j] += r1 + r3;
            }
            lsum += r0 * f0 + r1 * f1 + r2 * f2 + r3 * f3;
        }
    }
    #pragma unroll
    for (int off = 1; off < 4; off <<= 1) {
        #pragma unroll
        for (int i = 0; i < 2; i++) {
            rf[i][0] += __shfl_xor_sync(0xffffffffu, rf[i][0], off);
            rf[i][1] += __shfl_xor_sync(0xffffffffu, rf[i][1], off);
            rr[i][0] += __shfl_xor_sync(0xffffffffu, rr[i][0], off);
            rr[i][1] += __shfl_xor_sync(0xffffffffu, rr[i][1], off);
        }
    }
    if (t == 0) {
        #pragma unroll
        for (int i = 0; i < 2; i++) {
            int r0i = wm * 32 + i * 16 + g;
            atomicAdd(&red_f[r0i],     rf[i][0]);
            atomicAdd(&red_f[r0i + 8], rf[i][1]);
            atomicAdd(&red_r[r0i],     rr[i][0]);
            atomicAdd(&red_r[r0i + 8], rr[i][1]);
        }
    }
    if (SYM) {
        #pragma unroll
        for (int off = 4; off < 32; off <<= 1) {
            #pragma unroll
            for (int j = 0; j < 4; j++) {
                cf0[j] += __shfl_xor_sync(0xffffffffu, cf0[j], off);
                cf1[j] += __shfl_xor_sync(0xffffffffu, cf1[j], off);
                cr0[j] += __shfl_xor_sync(0xffffffffu, cr0[j], off);
                cr1[j] += __shfl_xor_sync(0xffffffffu, cr1[j], off);
            }
        }
        if (g == 0) {
            #pragma unroll
            for (int j = 0; j < 4; j++) {
                int c0i = wn * 32 + j * 8 + 2 * t;
                atomicAdd(&red_cf[c0i],     cf0[j]);
                atomicAdd(&red_cf[c0i + 1], cf1[j]);
                atomicAdd(&red_cr[c0i],     cr0[j]);
                atomicAdd(&red_cr[c0i + 1], cr1[j]);
            }
        }
    }
    #pragma unroll
    for (int off = 16; off; off >>= 1) lsum += __shfl_xor_sync(0xffffffffu, lsum, off);
    if (lane == 0) red_d[wid] = (double)lsum;
    __syncthreads();

    if (tid == 0) {
        double s = 0.0;
        #pragma unroll
        for (int w = 0; w < 16; w++) s += red_d[w];
        atomicAdd(&g_scal[slot], SYM ? 2.0 * s : s);
    }
    if (tid < 128) {
        int gi = slot * NB * NP + b * NP + p0 + tid;
        atomicAdd(&g_rowfd[gi], red_f[tid]);
        atomicAdd(&g_rowrc[gi], red_r[tid]);
        if (SYM) {
            int gj = slot * NB * NP + b * NP + q0 + tid;
            atomicAdd(&g_rowfd[gj], red_cf[tid]);
            atomicAdd(&g_rowrc[gj], red_cr[tid]);
        }
    }
}

// slots 1..3 full 8x8 tiling
__global__ void __launch_bounds__(512, 1) corr_mma_kernel()
{
    int slot = 1 + (blockIdx.z >> 4);
    int b    = blockIdx.z & 15;
    int p0   = blockIdx.y * 128;
    int q0   = blockIdx.x * 128;

    const __nv_bfloat16 *Bf, *Bc;
    switch (slot) {
        case 1:  Bf = g_F2p; Bc = g_C2p; break;
        case 2:  Bf = g_Fn0; Bc = g_Cn0; break;
        default: Bf = g_Fn1; Bc = g_Cn1; break;
    }
    corr_body<false>(slot, b, p0, q0,
                     g_F1 + (size_t)(b * NP + p0) * CF,
                     g_C1 + (size_t)(b * NP + p0) * CC,
                     Bf   + (size_t)(b * NP + q0) * CF,
                     Bc   + (size_t)(b * NP + q0) * CC);
}

// slot 0: x<28 -> strictly-upper pairs (symmetric), x>=28 -> diagonal tiles
__device__ const int8_t PAIR_P[36] = {0,0,0,0,0,0,0, 1,1,1,1,1,1, 2,2,2,2,2, 3,3,3,3, 4,4,4, 5,5, 6, 0,1,2,3,4,5,6,7};
__device__ const int8_t PAIR_Q[36] = {1,2,3,4,5,6,7, 2,3,4,5,6,7, 3,4,5,6,7, 4,5,6,7, 5,6,7, 6,7, 7, 0,1,2,3,4,5,6,7};

__global__ void __launch_bounds__(512, 1) corr_sym_kernel()
{
    int b  = blockIdx.z;
    int p0 = (int)PAIR_P[blockIdx.x] * 128;
    int q0 = (int)PAIR_Q[blockIdx.x] * 128;
    const __nv_bfloat16* Af = g_F1 + (size_t)(b * NP + p0) * CF;
    const __nv_bfloat16* Ac = g_C1 + (size_t)(b * NP + p0) * CC;
    const __nv_bfloat16* Bf = g_F1 + (size_t)(b * NP + q0) * CF;
    const __nv_bfloat16* Bc = g_C1 + (size_t)(b * NP + q0) * CC;
    if (blockIdx.x < 28) corr_body<true >(0, b, p0, q0, Af, Ac, Bf, Bc);
    else                 corr_body<false>(0, b, p0, q0, Af, Ac, Bf, Bc);
}

// ======================= finalize =======================
__global__ void finalize_kernel(float* out)
{
    __shared__ double sred[3][8];
    __shared__ double res[4][3];
    int tid = threadIdx.x;
    for (int s = 0; s < 4; s++) {
        double tf = 0.0, tr = 0.0, cx = 0.0;
        const float* rf = g_rowfd + s * NB * NP;
        const float* rr = g_rowrc + s * NB * NP;
        for (int i = tid; i < NB * NP; i += 256) {
            double f = (double)rf[i], r = (double)rr[i];
            tf += f; tr += r; cx += f * r;
        }
        #pragma unroll
        for (int off = 16; off; off >>= 1) {
            tf += __shfl_xor_sync(0xffffffffu, tf, off);
            tr += __shfl_xor_sync(0xffffffffu, tr, off);
            cx += __shfl_xor_sync(0xffffffffu, cx, off);
        }
        if ((tid & 31) == 0) { sred[0][tid >> 5] = tf; sred[1][tid >> 5] = tr; sred[2][tid >> 5] = cx; }
        __syncthreads();
        if (tid < 8) {
            double a = sred[0][tid], bv = sred[1][tid], c = sred[2][tid];
            #pragma unroll
            for (int off = 4; off; off >>= 1) {
                a  += __shfl_xor_sync(0xffu, a,  off);
                bv += __shfl_xor_sync(0xffu, bv, off);
                c  += __shfl_xor_sync(0xffu, c,  off);
            }
            if (tid == 0) { res[s][0] = a; res[s][1] = bv; res[s][2] = c; }
        }
        __syncthreads();
    }
    if (tid == 0) {
        const double BPQ = (double)NB * (double)NP * (double)NP;
        const double Q   = (double)NP;
        const double shifts[4] = {0.18, 0.12, 0.46, 0.46};
        double loss[4];
        for (int s = 0; s < 4; s++) {
            double tf = res[s][0], tr = res[s][1], cx = res[s][2];
            double A  = g_scal[s];
            double gm = tf / BPQ;
            loss[s] = (-A + cx / Q) / BPQ - (gm - shifts[s]) * (tr / BPQ);
        }
        out[0] = (float)loss[0];
        out[1] = (float)loss[1];
        out[2] = (float)(0.5 * (loss[2] + loss[3]));
    }
}

// ======================= launch =======================
extern "C" void kernel_launch(void* const* d_in, const int* in_sizes, int n_in,
                              void* d_out, int out_size)
{
    const float* orig_feats     = (const float*)d_in[0];
    const float* orig_feats_pos = (const float*)d_in[1];
    const float* orig_code      = (const float*)d_in[4];
    const float* orig_code_pos  = (const float*)d_in[5];
    const float* coords1        = (const float*)d_in[8];
    const float* coords2        = (const float*)d_in[9];
    const int*   perms          = (const int*)d_in[10];
    float* out = (float*)d_out;

    cudaFuncSetAttribute(corr_mma_kernel, cudaFuncAttributeMaxDynamicSharedMemorySize, SMEM_BYTES);
    cudaFuncSetAttribute(corr_sym_kernel, cudaFuncAttributeMaxDynamicSharedMemorySize, SMEM_BYTES);

    zero_kernel<<<256, 256>>>();

    dim3 tb(32, 8);
    transpose_kernel<<<dim3(25, CF / 64, NB), tb>>>(orig_feats,     0, CF);
    transpose_kernel<<<dim3(25, CC / 64, NB), tb>>>(orig_code,      1, CC);
    transpose_kernel<<<dim3(25, CF / 64, NB), tb>>>(orig_feats_pos, 2, CF);
    transpose_kernel<<<dim3(25, CC / 64, NB), tb>>>(orig_code_pos,  3, CC);

    sample_all_kernel<<<dim3(NB * NP, 4), 160>>>(coords1, coords2, perms);

    corr_mma_kernel<<<dim3(8, 8, 48), 512, SMEM_BYTES>>>();
    corr_sym_kernel<<<dim3(36, 1, 16), 512, SMEM_BYTES>>>();

    finalize_kernel<<<1, 256>>>(out);
}